// round 9
// baseline (speedup 1.0000x reference)
#include <cuda_runtime.h>
#include <cstdint>

// PermutationInvariantNet: B=8, N=256, IN_DIM=2, D=128, H=512, L=2
// Tokens T = B*N = 2048. fp32.
// 5 launches: embed, 2x { pool(stats+gemm+res+LN), ff(ff1+relu+ff2+res+LN) }.
// 512-thread GEMM cores, R4C1 (thread = 4 rows x 1 col), cp.async pipelining.
// Ping-pong: pool reads g_h -> writes g_hb; ff reads g_hb -> writes g_h/out.

#define T_TOK 2048
#define NB 8
#define NN 256
#define DD 128
#define HH 512
#define LN_EPS 1e-5f
#define NEG_INF -3.402823466e38f

__device__ __align__(16) float g_h[T_TOK * DD];    // buffer A (1 MB)
__device__ __align__(16) float g_hb[T_TOK * DD];   // buffer B (1 MB)

// -------- cp.async helpers --------
__device__ __forceinline__ void cp_async16(uint32_t dst, const void* src) {
    asm volatile("cp.async.cg.shared.global [%0], [%1], 16;" :: "r"(dst), "l"(src));
}
__device__ __forceinline__ void cp_commit() { asm volatile("cp.async.commit_group;"); }
__device__ __forceinline__ void cp_wait1()  { asm volatile("cp.async.wait_group 1;"); }
__device__ __forceinline__ void cp_wait0()  { asm volatile("cp.async.wait_group 0;"); }

// ===================== embed + LN (warp per token) =====================
// grid 128, block 512 = 16 warps; warp owns one token, lane owns d=lane+32j.
__global__ void __launch_bounds__(512)
embed_ln_kernel(const float* __restrict__ x, const float* __restrict__ We,
                const float* __restrict__ be, const float* __restrict__ ge,
                const float* __restrict__ bge) {
    int wid = threadIdx.x >> 5, lane = threadIdx.x & 31;
    int t = blockIdx.x * 16 + wid;
    float2 xx = *reinterpret_cast<const float2*>(x + t * 2);
    float y[4], s = 0.0f, q = 0.0f;
#pragma unroll
    for (int j = 0; j < 4; j++) {
        int d = lane + j * 32;
        y[j] = fmaf(xx.x, We[d], fmaf(xx.y, We[DD + d], be[d]));
        s += y[j];
        q += y[j] * y[j];
    }
#pragma unroll
    for (int o = 16; o > 0; o >>= 1) {
        s += __shfl_xor_sync(0xffffffffu, s, o);
        q += __shfl_xor_sync(0xffffffffu, q, o);
    }
    float mean = s * (1.0f / DD);
    float rstd = rsqrtf(q * (1.0f / DD) - mean * mean + LN_EPS);
#pragma unroll
    for (int j = 0; j < 4; j++) {
        int d = lane + j * 32;
        g_h[t * DD + d] = (y[j] - mean) * rstd * ge[d] + bge[d];
    }
}

// ===================== pool: stats + gemm + common + corr + res + LN =====
// grid 128 (16 tokens, all same batch), block 512 = 16 warps (4 rg x 4 cg).
// out = LN(h + h@Wt + [m1@Wb + sparse corr] + bp);  reads g_h, writes g_hb.
// smem float offsets:
//   As 0 [16][128] | Wt 2048 [128][128] | Wb 18432 [128][128]
//   slm1 34816 [4][128] | slm2 35328 | sli1 35840 | m1f 36352 | m2f 36480
//   cpart 36608 [4][128] | lnS 37120 [4][16] | lnQ 37184 | hitk 37248 [128]
//   hitl 37376 [128] | cnt 37504
#define POOL_SMEM (37508 * 4)
__global__ void __launch_bounds__(512)
pool_kernel(const float* __restrict__ Wp, const float* __restrict__ bp,
            const float* __restrict__ gp, const float* __restrict__ bgp) {
    extern __shared__ float sm[];
    float (*As)[DD]    = reinterpret_cast<float (*)[DD]>(sm);
    float* Wt          = sm + 2048;
    float* Wb          = sm + 18432;
    float (*slm1)[DD]  = reinterpret_cast<float (*)[DD]>(sm + 34816);
    float (*slm2)[DD]  = reinterpret_cast<float (*)[DD]>(sm + 35328);
    int   (*sli1)[DD]  = reinterpret_cast<int (*)[DD]>(sm + 35840);
    float* m1f         = sm + 36352;
    float* m2f         = sm + 36480;
    float (*cpart)[DD] = reinterpret_cast<float (*)[DD]>(sm + 36608);
    float (*lnS)[16]   = reinterpret_cast<float (*)[16]>(sm + 37120);
    float (*lnQ)[16]   = reinterpret_cast<float (*)[16]>(sm + 37184);
    int*   hitk        = reinterpret_cast<int*>(sm + 37248);
    int*   hitl        = reinterpret_cast<int*>(sm + 37376);
    int*   cnt         = reinterpret_cast<int*>(sm + 37504);

    const int tid = threadIdx.x;
    const int lane = tid & 31, wid = tid >> 5;
    const int cg = wid & 3, rg = wid >> 2;
    const int rg4 = rg * 4;
    const int c = cg * 32 + lane;
    const int row0 = blockIdx.x * 16;
    const int b = row0 >> 8;
    const int nbase = row0 & 255;

    // --- issue Wp cp.async: top 128 rows (group0), bottom 128 (group1) ---
    const uint32_t wts = (uint32_t)__cvta_generic_to_shared(Wt);
    const uint32_t wbs = (uint32_t)__cvta_generic_to_shared(Wb);
    const float* Wbot = Wp + DD * DD;
#pragma unroll
    for (int i = 0; i < 8; i++) {
        int t16 = tid + i * 512;                // 0..4095 float4s
        int k = t16 >> 5, c4 = (t16 & 31) << 2;
        cp_async16(wts + (uint32_t)(k * DD + c4) * 4, Wp + k * DD + c4);
    }
    cp_commit();
#pragma unroll
    for (int i = 0; i < 8; i++) {
        int t16 = tid + i * 512;
        int k = t16 >> 5, c4 = (t16 & 31) << 2;
        cp_async16(wbs + (uint32_t)(k * DD + c4) * 4, Wbot + k * DD + c4);
    }
    cp_commit();

    if (tid == 0) *cnt = 0;

    // --- load A tile (16 tokens; also the residual) ---
    {
        int i4 = tid * 4;
        *reinterpret_cast<float4*>(&As[i4 >> 7][i4 & 127]) =
            *reinterpret_cast<const float4*>(&g_h[row0 * DD + i4]);
    }

    // --- batch stats scan (overlaps cp.async): d = tid&127, slice = tid>>7 ---
    {
        int d = tid & 127, sl = tid >> 7;
        const float* hb = g_h + b * NN * DD;
        float m1 = NEG_INF, m2 = NEG_INF;
        int i1 = 0;
        int n0 = sl * 64;
#pragma unroll 8
        for (int n = n0; n < n0 + 64; n++) {
            float v = hb[n * DD + d];
            if (v > m1) { m2 = m1; m1 = v; i1 = n; }
            else if (v > m2) { m2 = v; }
        }
        slm1[sl][d] = m1; slm2[sl][d] = m2; sli1[sl][d] = i1;
    }

    cp_wait1();          // Wt ready
    __syncthreads();     // + As, slices, cnt visible

    // --- merge slice stats + build hit list (threads 0..127) ---
    if (tid < DD) {
        float m1 = slm1[0][tid], m2 = slm2[0][tid];
        int i1 = sli1[0][tid];
#pragma unroll
        for (int j = 1; j < 4; j++) {
            float a1 = slm1[j][tid], a2 = slm2[j][tid];
            int ai = sli1[j][tid];
            if (a1 > m1) { m2 = fmaxf(m1, a2); m1 = a1; i1 = ai; }
            else         { m2 = fmaxf(m2, a1); }
        }
        m1f[tid] = m1; m2f[tid] = m2;
        int l = i1 - nbase;
        if (l >= 0 && l < 16) {
            int idx = atomicAdd(cnt, 1);
            hitk[idx] = tid; hitl[idx] = l;
        }
    }

    // --- GEMM: acc = As(16x128) @ Wt(128x128), R4C1 ---
    float acc[4] = {0.f, 0.f, 0.f, 0.f};
#pragma unroll 8
    for (int k0 = 0; k0 < DD; k0 += 4) {
        float av[4][4];
#pragma unroll
        for (int r = 0; r < 4; r++)
            *reinterpret_cast<float4*>(av[r]) =
                *reinterpret_cast<const float4*>(&As[rg4 + r][k0]);
#pragma unroll
        for (int kk = 0; kk < 4; kk++) {
            float w = Wt[(k0 + kk) * DD + c];
#pragma unroll
            for (int r = 0; r < 4; r++)
                acc[r] = fmaf(av[r][kk], w, acc[r]);
        }
    }

    cp_wait0();          // Wb ready
    __syncthreads();     // + merged stats, hit list visible

    // --- common = m1 @ Wb, split over the 4 rowgroups ---
    {
        float p = 0.0f;
        int k0 = rg * 32;
#pragma unroll 8
        for (int k = k0; k < k0 + 32; k++)
            p = fmaf(m1f[k], Wb[k * DD + c], p);
        cpart[rg][c] = p;
    }
    __syncthreads();

    // --- epilogue: common + sparse corr + bias + residual + LN ---
    float common = cpart[0][c] + cpart[1][c] + cpart[2][c] + cpart[3][c];
    float corr[4] = {0.f, 0.f, 0.f, 0.f};
    int nh = *cnt;
    for (int j = 0; j < nh; j++) {
        int k = hitk[j], l = hitl[j];
        if ((l >> 2) == rg)
            corr[l & 3] += (m2f[k] - m1f[k]) * Wb[k * DD + c];
    }
    float bpc = bp[c];
    float v[4], s[4], q[4];
#pragma unroll
    for (int r = 0; r < 4; r++) {
        v[r] = acc[r] + common + corr[r] + bpc + As[rg4 + r][c];
        s[r] = v[r];
        q[r] = v[r] * v[r];
    }
#pragma unroll
    for (int o = 16; o > 0; o >>= 1)
#pragma unroll
        for (int r = 0; r < 4; r++) {
            s[r] += __shfl_xor_sync(0xffffffffu, s[r], o);
            q[r] += __shfl_xor_sync(0xffffffffu, q[r], o);
        }
    if (lane == 0)
#pragma unroll
        for (int r = 0; r < 4; r++) { lnS[cg][rg4 + r] = s[r]; lnQ[cg][rg4 + r] = q[r]; }
    __syncthreads();
    float gc = gp[c], ec = bgp[c];
#pragma unroll
    for (int r = 0; r < 4; r++) {
        int row = rg4 + r;
        float S = lnS[0][row] + lnS[1][row] + lnS[2][row] + lnS[3][row];
        float Q = lnQ[0][row] + lnQ[1][row] + lnQ[2][row] + lnQ[3][row];
        float mean = S * (1.0f / DD);
        float rstd = rsqrtf(Q * (1.0f / DD) - mean * mean + LN_EPS);
        g_hb[(row0 + row) * DD + c] = (v[r] - mean) * rstd * gc + ec;
    }
}

// ===================== fused FF =====================
// h' = LN(h + relu(h@W1+b1)@W2 + b2); reads g_hb, writes g_h (or out).
// grid 128 (16 tokens), block 512. 4 H-chunks of 128; W1 double-buffered.
// smem floats: hs 0 [16][128] | W1c 2048 [2][128][128] | W2c 34816 [128][128]
//              | Us 51200 [16][128] | lnS 53248 [4][16] | lnQ 53312
#define FF_SMEM (53376 * 4)
template <bool FINAL>
__global__ void __launch_bounds__(512)
ff_fused_kernel(const float* __restrict__ W1, const float* __restrict__ b1,
                const float* __restrict__ W2, const float* __restrict__ b2,
                const float* __restrict__ gf, const float* __restrict__ bgf,
                float* __restrict__ out) {
    extern __shared__ float sm[];
    float (*hs)[DD]  = reinterpret_cast<float (*)[DD]>(sm);
    float* W1c       = sm + 2048;
    float* W2c       = sm + 34816;
    float (*Us)[DD]  = reinterpret_cast<float (*)[DD]>(sm + 51200);
    float (*lnS)[16] = reinterpret_cast<float (*)[16]>(sm + 53248);
    float (*lnQ)[16] = reinterpret_cast<float (*)[16]>(sm + 53312);

    const int tid = threadIdx.x;
    const int lane = tid & 31, wid = tid >> 5;
    const int cg = wid & 3, rg = wid >> 2;
    const int rg4 = rg * 4;
    const int c = cg * 32 + lane;
    const int row0 = blockIdx.x * 16;

    const uint32_t w1s = (uint32_t)__cvta_generic_to_shared(W1c);
    const uint32_t w2s = (uint32_t)__cvta_generic_to_shared(W2c);

    // issue chunk-0 weight loads
#pragma unroll
    for (int i = 0; i < 8; i++) {               // W1 chunk 0 -> buf 0
        int t16 = tid + i * 512;
        int k = t16 >> 5, c4 = (t16 & 31) << 2;
        cp_async16(w1s + (uint32_t)(k * DD + c4) * 4, W1 + k * HH + c4);
    }
    cp_commit();
#pragma unroll
    for (int i = 0; i < 8; i++) {               // W2 chunk 0
        int t16 = tid + i * 512;
        int k = t16 >> 5, c4 = (t16 & 31) << 2;
        cp_async16(w2s + (uint32_t)(k * DD + c4) * 4, W2 + k * DD + c4);
    }
    cp_commit();

    // load h rows (doubles as residual)
    {
        int i4 = tid * 4;
        *reinterpret_cast<float4*>(&hs[i4 >> 7][i4 & 127]) =
            *reinterpret_cast<const float4*>(&g_hb[row0 * DD + i4]);
    }

    float acc2[4] = {0.f, 0.f, 0.f, 0.f};

    for (int ci = 0; ci < 4; ci++) {
        const int c0 = ci * 128;
        const float* W1b = W1c + (ci & 1) * 16384;

        cp_wait1();          // W1(ci) landed (W2(ci) may still fly)
        __syncthreads();     // + hs / Us / buffer hazards

        // ---- ff1: acc1 = hs @ W1b (R4C1) ----
        float acc1[4] = {0.f, 0.f, 0.f, 0.f};
#pragma unroll 8
        for (int k0 = 0; k0 < DD; k0 += 4) {
            float av[4][4];
#pragma unroll
            for (int r = 0; r < 4; r++)
                *reinterpret_cast<float4*>(av[r]) =
                    *reinterpret_cast<const float4*>(&hs[rg4 + r][k0]);
#pragma unroll
            for (int kk = 0; kk < 4; kk++) {
                float w = W1b[(k0 + kk) * DD + c];
#pragma unroll
                for (int r = 0; r < 4; r++)
                    acc1[r] = fmaf(av[r][kk], w, acc1[r]);
            }
        }
        {
            float bb = b1[c0 + c];
#pragma unroll
            for (int r = 0; r < 4; r++)
                Us[rg4 + r][c] = fmaxf(acc1[r] + bb, 0.0f);
        }

        // prefetch W1(ci+1) into the other buffer (overlaps ff2)
        if (ci < 3) {
            uint32_t dst = w1s + (uint32_t)(((ci + 1) & 1) * 16384) * 4;
            const float* src = W1 + c0 + 128;
#pragma unroll
            for (int i = 0; i < 8; i++) {
                int t16 = tid + i * 512;
                int k = t16 >> 5, c4 = (t16 & 31) << 2;
                cp_async16(dst + (uint32_t)(k * DD + c4) * 4, src + k * HH + c4);
            }
            cp_commit();
        }

        if (ci < 3) cp_wait1(); else cp_wait0();   // W2(ci) landed
        __syncthreads();                            // + Us visible

        // ---- ff2 partial: acc2 += Us @ W2c (R4C1) ----
#pragma unroll 8
        for (int k0 = 0; k0 < DD; k0 += 4) {
            float av[4][4];
#pragma unroll
            for (int r = 0; r < 4; r++)
                *reinterpret_cast<float4*>(av[r]) =
                    *reinterpret_cast<const float4*>(&Us[rg4 + r][k0]);
#pragma unroll
            for (int kk = 0; kk < 4; kk++) {
                float w = W2c[(k0 + kk) * DD + c];
#pragma unroll
                for (int r = 0; r < 4; r++)
                    acc2[r] = fmaf(av[r][kk], w, acc2[r]);
            }
        }
        __syncthreads();    // W2c fully consumed

        // prefetch W2(ci+1) (overlaps next ff1)
        if (ci < 3) {
            const float* src = W2 + (c0 + 128) * DD;
#pragma unroll
            for (int i = 0; i < 8; i++) {
                int t16 = tid + i * 512;
                int k = t16 >> 5, c4 = (t16 & 31) << 2;
                cp_async16(w2s + (uint32_t)(k * DD + c4) * 4, src + k * DD + c4);
            }
            cp_commit();
        }
    }

    // epilogue: +b2 +residual (hs), LN (warp partial + 4-way combine)
    float b2c = b2[c];
    float v[4], s[4], q[4];
#pragma unroll
    for (int r = 0; r < 4; r++) {
        v[r] = acc2[r] + b2c + hs[rg4 + r][c];
        s[r] = v[r];
        q[r] = v[r] * v[r];
    }
#pragma unroll
    for (int o = 16; o > 0; o >>= 1)
#pragma unroll
        for (int r = 0; r < 4; r++) {
            s[r] += __shfl_xor_sync(0xffffffffu, s[r], o);
            q[r] += __shfl_xor_sync(0xffffffffu, q[r], o);
        }
    if (lane == 0)
#pragma unroll
        for (int r = 0; r < 4; r++) { lnS[cg][rg4 + r] = s[r]; lnQ[cg][rg4 + r] = q[r]; }
    __syncthreads();
    float gc = gf[c], ec = bgf[c];
#pragma unroll
    for (int r = 0; r < 4; r++) {
        int row = rg4 + r;
        float S = lnS[0][row] + lnS[1][row] + lnS[2][row] + lnS[3][row];
        float Q = lnQ[0][row] + lnQ[1][row] + lnQ[2][row] + lnQ[3][row];
        float mean = S * (1.0f / DD);
        float rstd = rsqrtf(Q * (1.0f / DD) - mean * mean + LN_EPS);
        float rv = (v[r] - mean) * rstd * gc + ec;
        if (FINAL) out[(row0 + row) * DD + c] = rv;
        else       g_h[(row0 + row) * DD + c] = rv;
    }
}

extern "C" void kernel_launch(void* const* d_in, const int* in_sizes, int n_in,
                              void* d_out, int out_size) {
    const float* x   = (const float*)d_in[0];   // (8,256,2)
    const float* We  = (const float*)d_in[1];   // (2,128)
    const float* be  = (const float*)d_in[2];
    const float* ge  = (const float*)d_in[3];
    const float* bge = (const float*)d_in[4];
    const float* Wp  = (const float*)d_in[5];   // (2,256,128)
    const float* bp  = (const float*)d_in[6];
    const float* gp  = (const float*)d_in[7];
    const float* bgp = (const float*)d_in[8];
    const float* W1  = (const float*)d_in[9];   // (2,128,512)
    const float* b1  = (const float*)d_in[10];
    const float* W2  = (const float*)d_in[11];  // (2,512,128)
    const float* b2  = (const float*)d_in[12];
    const float* gf  = (const float*)d_in[13];
    const float* bgf = (const float*)d_in[14];
    float* out = (float*)d_out;                 // (8,256,128) fp32

    cudaFuncSetAttribute(pool_kernel,
                         cudaFuncAttributeMaxDynamicSharedMemorySize, POOL_SMEM);
    cudaFuncSetAttribute(ff_fused_kernel<false>,
                         cudaFuncAttributeMaxDynamicSharedMemorySize, FF_SMEM);
    cudaFuncSetAttribute(ff_fused_kernel<true>,
                         cudaFuncAttributeMaxDynamicSharedMemorySize, FF_SMEM);

    embed_ln_kernel<<<T_TOK / 16, 512>>>(x, We, be, ge, bge);

    for (int i = 0; i < 2; i++) {
        pool_kernel<<<T_TOK / 16, 512, POOL_SMEM>>>(
            Wp + i * 2 * DD * DD, bp + i * DD, gp + i * DD, bgp + i * DD);

        if (i == 1)
            ff_fused_kernel<true><<<T_TOK / 16, 512, FF_SMEM>>>(
                W1 + i * DD * HH, b1 + i * HH, W2 + i * HH * DD, b2 + i * DD,
                gf + i * DD, bgf + i * DD, out);
        else
            ff_fused_kernel<false><<<T_TOK / 16, 512, FF_SMEM>>>(
                W1 + i * DD * HH, b1 + i * HH, W2 + i * HH * DD, b2 + i * DD,
                gf + i * DD, bgf + i * DD, nullptr);
    }
}

// round 11
// speedup vs baseline: 1.6955x; 1.6955x over previous
#include <cuda_runtime.h>
#include <cstdint>

// PermutationInvariantNet: B=8, N=256, IN_DIM=2, D=128, H=512, L=2
// Tokens T = B*N = 2048. fp32.
// 5 launches: embed, 2x { pool(stats+gemm+res+LN), ff(ff1+relu+ff2+res+LN) }.
// GEMM core (proven R6 economy): 256 thr, thread = 4 rows x 2 cols
// (crossbar 32 wf/k == FFMA 32 cyc/k), cp.async weight pipelining,
// explicit register double-buffering on A/W fragments.
// Ping-pong: pool reads g_h -> writes g_hb; ff reads g_hb -> writes g_h/out.

#define T_TOK 2048
#define NB 8
#define NN 256
#define DD 128
#define HH 512
#define LN_EPS 1e-5f
#define NEG_INF -3.402823466e38f

__device__ __align__(16) float g_h[T_TOK * DD];    // buffer A (1 MB)
__device__ __align__(16) float g_hb[T_TOK * DD];   // buffer B (1 MB)

// -------- cp.async helpers --------
__device__ __forceinline__ void cp_async16(uint32_t dst, const void* src) {
    asm volatile("cp.async.cg.shared.global [%0], [%1], 16;" :: "r"(dst), "l"(src));
}
__device__ __forceinline__ void cp_commit() { asm volatile("cp.async.commit_group;"); }
__device__ __forceinline__ void cp_wait1()  { asm volatile("cp.async.wait_group 1;"); }
__device__ __forceinline__ void cp_wait0()  { asm volatile("cp.async.wait_group 0;"); }

// ===================== embed + LN =====================
__global__ void __launch_bounds__(128)
embed_ln_kernel(const float* __restrict__ x, const float* __restrict__ We,
                const float* __restrict__ be, const float* __restrict__ ge,
                const float* __restrict__ bge) {
    __shared__ float sh[8];
    int t = blockIdx.x, d = threadIdx.x;
    float x0 = x[t * 2 + 0];
    float x1 = x[t * 2 + 1];
    float y = fmaf(x0, We[d], fmaf(x1, We[DD + d], be[d]));
    float s = y, q = y * y;
#pragma unroll
    for (int o = 16; o > 0; o >>= 1) {
        s += __shfl_xor_sync(0xffffffffu, s, o);
        q += __shfl_xor_sync(0xffffffffu, q, o);
    }
    int lane = threadIdx.x & 31, w = threadIdx.x >> 5;
    if (lane == 0) { sh[w] = s; sh[4 + w] = q; }
    __syncthreads();
    s = sh[0] + sh[1] + sh[2] + sh[3];
    q = sh[4] + sh[5] + sh[6] + sh[7];
    float mean = s * (1.0f / DD);
    float rstd = rsqrtf(q * (1.0f / DD) - mean * mean + LN_EPS);
    g_h[t * DD + d] = (y - mean) * rstd * ge[d] + bge[d];
}

// ===================== pool: stats + gemm + res + LN =====================
// h' = LN(h + [h, loo(h)] @ Wp + bp); reads g_h, writes g_hb.
// grid 128 (16 tokens, one batch each), block 256 (R6 GEMM economy:
// 8 warps = 4 rowgroups x 2 colgroups, thread = 4 rows x 2 cols).
// In-kernel stats: 2 slices x 128 features scan the batch slab of g_h
// (previous kernel's output -> no race; own writes go to g_hb).
// smem float offsets:
//   As 0 [16][256]=4096 | Ws 4096 [256][128]=32768 | lnS 36864 [2][16]
//   lnQ 36896 | slm1 36928 [2][128] | slm2 37184 | sli1 37440 (int)
//   m1f 37696 [128] | m2f 37824 [128] | i1f 37952 [128] (int)
#define POOL_SMEM (38080 * 4)
__global__ void __launch_bounds__(256, 1)
pool_kernel(const float* __restrict__ Wp, const float* __restrict__ bp,
            const float* __restrict__ gp, const float* __restrict__ bgp) {
    extern __shared__ float sm[];
    float (*As)[256]  = reinterpret_cast<float (*)[256]>(sm);
    float (*Ws)[DD]   = reinterpret_cast<float (*)[DD]>(sm + 4096);
    float (*lnS)[16]  = reinterpret_cast<float (*)[16]>(sm + 36864);
    float (*lnQ)[16]  = reinterpret_cast<float (*)[16]>(sm + 36896);
    float (*slm1)[DD] = reinterpret_cast<float (*)[DD]>(sm + 36928);
    float (*slm2)[DD] = reinterpret_cast<float (*)[DD]>(sm + 37184);
    int   (*sli1)[DD] = reinterpret_cast<int (*)[DD]>(sm + 37440);
    float* m1f        = sm + 37696;
    float* m2f        = sm + 37824;
    int*   i1f        = reinterpret_cast<int*>(sm + 37952);

    const int tid = threadIdx.x;
    const int lane = tid & 31, wid = tid >> 5;
    const int rg = wid & 3, cg = wid >> 2;
    const int rg4 = rg * 4;
    const int c2 = cg * 64 + lane * 2;
    const int row0 = blockIdx.x * 16;
    const int b = row0 >> 8;
    const int nbase = row0 & 255;

    // --- issue Wp cp.async in 2 halves (groups 0 and 1) ---
    uint32_t ws_base = (uint32_t)__cvta_generic_to_shared(&Ws[0][0]);
#pragma unroll
    for (int h = 0; h < 2; h++) {
#pragma unroll
        for (int i = 0; i < 16; i++) {
            int t16 = tid + i * 256;            // 0..4095 float4s
            int k = h * 128 + (t16 >> 5);
            int c4 = (t16 & 31) << 2;
            cp_async16(ws_base + (uint32_t)(k * DD + c4) * 4, Wp + k * DD + c4);
        }
        cp_commit();
    }

    // --- As h-part (cols 0..127); also the residual ---
#pragma unroll
    for (int i = 0; i < 2; i++) {
        int idx4 = (tid + i * 256) * 4;
        int r = idx4 >> 7, k = idx4 & 127;
        *reinterpret_cast<float4*>(&As[r][k]) =
            *reinterpret_cast<const float4*>(&g_h[row0 * DD + idx4]);
    }

    // --- stats scan (overlaps cp.async): slice = tid>>7, d = tid&127 ---
    {
        int d = tid & 127, sl = tid >> 7;
        const float* hb = g_h + b * NN * DD;
        float m1 = NEG_INF, m2 = NEG_INF;
        int i1 = 0;
        int n0 = sl * 128;
#pragma unroll 8
        for (int n = n0; n < n0 + 128; n++) {
            float v = hb[n * DD + d];
            if (v > m1) { m2 = m1; m1 = v; i1 = n; }
            else if (v > m2) { m2 = v; }
        }
        slm1[sl][d] = m1; slm2[sl][d] = m2; sli1[sl][d] = i1;
    }
    __syncthreads();

    // --- merge 2 slices (threads 0..127); earlier-slice argmax wins ties ---
    if (tid < DD) {
        float m1 = slm1[0][tid], m2 = slm2[0][tid];
        int i1 = sli1[0][tid];
        float a1 = slm1[1][tid], a2 = slm2[1][tid];
        int ai = sli1[1][tid];
        if (a1 > m1) { m2 = fmaxf(m1, a2); m1 = a1; i1 = ai; }
        else         { m2 = fmaxf(m2, a1); }
        m1f[tid] = m1; m2f[tid] = m2; i1f[tid] = i1;
    }
    __syncthreads();

    // --- As pooled part (cols 128..255) from merged stats ---
#pragma unroll
    for (int i = 0; i < 8; i++) {
        int idx = tid + i * 256;                // 0..2047
        int r = idx >> 7, k = idx & 127;
        As[r][128 + k] = (nbase + r == i1f[k]) ? m2f[k] : m1f[k];
    }

    float acc[4][2];
#pragma unroll
    for (int r = 0; r < 4; r++) { acc[r][0] = 0.f; acc[r][1] = 0.f; }

    cp_wait1();          // Wp half 1 ready
    __syncthreads();     // + As complete

    // --- GEMM half 1: k in [0,128), register double-buffered ---
    {
        float4 av[4]; float2 wv[4];
#pragma unroll
        for (int r = 0; r < 4; r++)
            av[r] = *reinterpret_cast<const float4*>(&As[rg4 + r][0]);
#pragma unroll
        for (int kk = 0; kk < 4; kk++)
            wv[kk] = *reinterpret_cast<const float2*>(&Ws[kk][c2]);
#pragma unroll 2
        for (int k0 = 0; k0 < 128; k0 += 4) {
            float4 avn[4]; float2 wvn[4];
            int kn = k0 + 4;
            if (kn < 128) {
#pragma unroll
                for (int r = 0; r < 4; r++)
                    avn[r] = *reinterpret_cast<const float4*>(&As[rg4 + r][kn]);
#pragma unroll
                for (int kk = 0; kk < 4; kk++)
                    wvn[kk] = *reinterpret_cast<const float2*>(&Ws[kn + kk][c2]);
            }
            float am[4][4];
#pragma unroll
            for (int r = 0; r < 4; r++) {
                am[r][0] = av[r].x; am[r][1] = av[r].y;
                am[r][2] = av[r].z; am[r][3] = av[r].w;
            }
#pragma unroll
            for (int kk = 0; kk < 4; kk++) {
                float2 w = wv[kk];
#pragma unroll
                for (int r = 0; r < 4; r++) {
                    acc[r][0] = fmaf(am[r][kk], w.x, acc[r][0]);
                    acc[r][1] = fmaf(am[r][kk], w.y, acc[r][1]);
                }
            }
#pragma unroll
            for (int r = 0; r < 4; r++) av[r] = avn[r];
#pragma unroll
            for (int kk = 0; kk < 4; kk++) wv[kk] = wvn[kk];
        }
    }

    cp_wait0();          // Wp half 2 ready
    __syncthreads();

    // --- GEMM half 2: k in [128,256) ---
    {
        float4 av[4]; float2 wv[4];
#pragma unroll
        for (int r = 0; r < 4; r++)
            av[r] = *reinterpret_cast<const float4*>(&As[rg4 + r][128]);
#pragma unroll
        for (int kk = 0; kk < 4; kk++)
            wv[kk] = *reinterpret_cast<const float2*>(&Ws[128 + kk][c2]);
#pragma unroll 2
        for (int k0 = 128; k0 < 256; k0 += 4) {
            float4 avn[4]; float2 wvn[4];
            int kn = k0 + 4;
            if (kn < 256) {
#pragma unroll
                for (int r = 0; r < 4; r++)
                    avn[r] = *reinterpret_cast<const float4*>(&As[rg4 + r][kn]);
#pragma unroll
                for (int kk = 0; kk < 4; kk++)
                    wvn[kk] = *reinterpret_cast<const float2*>(&Ws[kn + kk][c2]);
            }
            float am[4][4];
#pragma unroll
            for (int r = 0; r < 4; r++) {
                am[r][0] = av[r].x; am[r][1] = av[r].y;
                am[r][2] = av[r].z; am[r][3] = av[r].w;
            }
#pragma unroll
            for (int kk = 0; kk < 4; kk++) {
                float2 w = wv[kk];
#pragma unroll
                for (int r = 0; r < 4; r++) {
                    acc[r][0] = fmaf(am[r][kk], w.x, acc[r][0]);
                    acc[r][1] = fmaf(am[r][kk], w.y, acc[r][1]);
                }
            }
#pragma unroll
            for (int r = 0; r < 4; r++) av[r] = avn[r];
#pragma unroll
            for (int kk = 0; kk < 4; kk++) wv[kk] = wvn[kk];
        }
    }

    // --- epilogue: +bias +residual, LN (warp partial + 2-way combine) ---
    float v[4][2], s[4], q[4];
    float bp0 = bp[c2], bp1 = bp[c2 + 1];
#pragma unroll
    for (int r = 0; r < 4; r++) {
        v[r][0] = acc[r][0] + bp0 + As[rg4 + r][c2];
        v[r][1] = acc[r][1] + bp1 + As[rg4 + r][c2 + 1];
        s[r] = v[r][0] + v[r][1];
        q[r] = v[r][0] * v[r][0] + v[r][1] * v[r][1];
    }
#pragma unroll
    for (int o = 16; o > 0; o >>= 1)
#pragma unroll
        for (int r = 0; r < 4; r++) {
            s[r] += __shfl_xor_sync(0xffffffffu, s[r], o);
            q[r] += __shfl_xor_sync(0xffffffffu, q[r], o);
        }
    if (lane == 0)
#pragma unroll
        for (int r = 0; r < 4; r++) { lnS[cg][rg4 + r] = s[r]; lnQ[cg][rg4 + r] = q[r]; }
    __syncthreads();
    float g0 = gp[c2], g1 = gp[c2 + 1], e0 = bgp[c2], e1 = bgp[c2 + 1];
#pragma unroll
    for (int r = 0; r < 4; r++) {
        float S = lnS[0][rg4 + r] + lnS[1][rg4 + r];
        float Q = lnQ[0][rg4 + r] + lnQ[1][rg4 + r];
        float mean = S * (1.0f / DD);
        float rstd = rsqrtf(Q * (1.0f / DD) - mean * mean + LN_EPS);
        float2 o;
        o.x = (v[r][0] - mean) * rstd * g0 + e0;
        o.y = (v[r][1] - mean) * rstd * g1 + e1;
        *reinterpret_cast<float2*>(&g_hb[(row0 + rg4 + r) * DD + c2]) = o;
    }
}

// ===================== fused FF =====================
// h' = LN(h + relu(h@W1+b1)@W2 + b2); reads g_hb, writes g_h (or out).
// R6 pipeline: 4 H-chunks of 128, W1 double-buffered, W2 single, cp.async.
// smem floats: hs 0 [16][128] | W1c 2048 [2][128][128] | W2c 34816 [128][128]
//              | Us 51200 [16][128] | lnS 53248 [2][16] | lnQ 53280
#define FF_SMEM (53312 * 4)
template <bool FINAL>
__global__ void __launch_bounds__(256, 1)
ff_fused_kernel(const float* __restrict__ W1, const float* __restrict__ b1,
                const float* __restrict__ W2, const float* __restrict__ b2,
                const float* __restrict__ gf, const float* __restrict__ bgf,
                float* __restrict__ out) {
    extern __shared__ float sm[];
    float (*hs)[DD]  = reinterpret_cast<float (*)[DD]>(sm);
    float* W1c       = sm + 2048;
    float (*W2c)[DD] = reinterpret_cast<float (*)[DD]>(sm + 34816);
    float (*Us)[DD]  = reinterpret_cast<float (*)[DD]>(sm + 51200);
    float (*lnS)[16] = reinterpret_cast<float (*)[16]>(sm + 53248);
    float (*lnQ)[16] = reinterpret_cast<float (*)[16]>(sm + 53280);

    const int tid = threadIdx.x;
    const int lane = tid & 31, wid = tid >> 5;
    const int rg = wid & 3, cg = wid >> 2;
    const int rg4 = rg * 4;
    const int c2 = cg * 64 + lane * 2;
    const int row0 = blockIdx.x * 16;

    const uint32_t w1s = (uint32_t)__cvta_generic_to_shared(W1c);
    const uint32_t w2s = (uint32_t)__cvta_generic_to_shared(&W2c[0][0]);

    // chunk-0 weight loads
#pragma unroll
    for (int i = 0; i < 16; i++) {               // W1 chunk 0 -> buf 0
        int t16 = tid + i * 256;
        int k = t16 >> 5, c4 = (t16 & 31) << 2;
        cp_async16(w1s + (uint32_t)(k * DD + c4) * 4, W1 + k * HH + c4);
    }
    cp_commit();
#pragma unroll
    for (int i = 0; i < 16; i++) {               // W2 chunk 0
        int t16 = tid + i * 256;
        int k = t16 >> 5, c4 = (t16 & 31) << 2;
        cp_async16(w2s + (uint32_t)(k * DD + c4) * 4, W2 + k * DD + c4);
    }
    cp_commit();

    // load h rows (doubles as residual)
#pragma unroll
    for (int i = 0; i < 2; i++) {
        int idx4 = (tid + i * 256) * 4;
        *reinterpret_cast<float4*>(&hs[idx4 >> 7][idx4 & 127]) =
            *reinterpret_cast<const float4*>(&g_hb[row0 * DD + idx4]);
    }

    float acc2[4][2];
#pragma unroll
    for (int r = 0; r < 4; r++) { acc2[r][0] = 0.f; acc2[r][1] = 0.f; }

    for (int ci = 0; ci < 4; ci++) {
        const int c0 = ci * 128;
        const float* W1b = W1c + (ci & 1) * 16384;

        cp_wait1();          // W1(ci) landed
        __syncthreads();     // + hs / Us / buffer hazards

        // ---- ff1: acc1 = hs @ W1b, register double-buffered ----
        float acc1[4][2];
#pragma unroll
        for (int r = 0; r < 4; r++) { acc1[r][0] = 0.f; acc1[r][1] = 0.f; }
        {
            float4 av[4]; float2 wv[4];
#pragma unroll
            for (int r = 0; r < 4; r++)
                av[r] = *reinterpret_cast<const float4*>(&hs[rg4 + r][0]);
#pragma unroll
            for (int kk = 0; kk < 4; kk++)
                wv[kk] = *reinterpret_cast<const float2*>(&W1b[kk * DD + c2]);
#pragma unroll 2
            for (int k0 = 0; k0 < DD; k0 += 4) {
                float4 avn[4]; float2 wvn[4];
                int kn = k0 + 4;
                if (kn < DD) {
#pragma unroll
                    for (int r = 0; r < 4; r++)
                        avn[r] = *reinterpret_cast<const float4*>(&hs[rg4 + r][kn]);
#pragma unroll
                    for (int kk = 0; kk < 4; kk++)
                        wvn[kk] = *reinterpret_cast<const float2*>(&W1b[(kn + kk) * DD + c2]);
                }
                float am[4][4];
#pragma unroll
                for (int r = 0; r < 4; r++) {
                    am[r][0] = av[r].x; am[r][1] = av[r].y;
                    am[r][2] = av[r].z; am[r][3] = av[r].w;
                }
#pragma unroll
                for (int kk = 0; kk < 4; kk++) {
                    float2 w = wv[kk];
#pragma unroll
                    for (int r = 0; r < 4; r++) {
                        acc1[r][0] = fmaf(am[r][kk], w.x, acc1[r][0]);
                        acc1[r][1] = fmaf(am[r][kk], w.y, acc1[r][1]);
                    }
                }
#pragma unroll
                for (int r = 0; r < 4; r++) av[r] = avn[r];
#pragma unroll
                for (int kk = 0; kk < 4; kk++) wv[kk] = wvn[kk];
            }
        }
        // Us = relu(acc1 + b1)
        {
            float bb0 = b1[c0 + c2], bb1 = b1[c0 + c2 + 1];
#pragma unroll
            for (int r = 0; r < 4; r++) {
                float2 u;
                u.x = fmaxf(acc1[r][0] + bb0, 0.0f);
                u.y = fmaxf(acc1[r][1] + bb1, 0.0f);
                *reinterpret_cast<float2*>(&Us[rg4 + r][c2]) = u;
            }
        }

        // prefetch W1(ci+1) into the other buffer (overlaps ff2)
        if (ci < 3) {
            uint32_t dst = w1s + (uint32_t)(((ci + 1) & 1) * 16384) * 4;
            const float* src = W1 + c0 + 128;
#pragma unroll
            for (int i = 0; i < 16; i++) {
                int t16 = tid + i * 256;
                int k = t16 >> 5, c4 = (t16 & 31) << 2;
                cp_async16(dst + (uint32_t)(k * DD + c4) * 4, src + k * HH + c4);
            }
            cp_commit();
        }

        if (ci < 3) cp_wait1(); else cp_wait0();   // W2(ci) landed
        __syncthreads();                            // + Us visible

        // ---- ff2 partial: acc2 += Us @ W2c, register double-buffered ----
        {
            float4 av[4]; float2 wv[4];
#pragma unroll
            for (int r = 0; r < 4; r++)
                av[r] = *reinterpret_cast<const float4*>(&Us[rg4 + r][0]);
#pragma unroll
            for (int kk = 0; kk < 4; kk++)
                wv[kk] = *reinterpret_cast<const float2*>(&W2c[kk][c2]);
#pragma unroll 2
            for (int k0 = 0; k0 < DD; k0 += 4) {
                float4 avn[4]; float2 wvn[4];
                int kn = k0 + 4;
                if (kn < DD) {
#pragma unroll
                    for (int r = 0; r < 4; r++)
                        avn[r] = *reinterpret_cast<const float4*>(&Us[rg4 + r][kn]);
#pragma unroll
                    for (int kk = 0; kk < 4; kk++)
                        wvn[kk] = *reinterpret_cast<const float2*>(&W2c[kn + kk][c2]);
                }
                float am[4][4];
#pragma unroll
                for (int r = 0; r < 4; r++) {
                    am[r][0] = av[r].x; am[r][1] = av[r].y;
                    am[r][2] = av[r].z; am[r][3] = av[r].w;
                }
#pragma unroll
                for (int kk = 0; kk < 4; kk++) {
                    float2 w = wv[kk];
#pragma unroll
                    for (int r = 0; r < 4; r++) {
                        acc2[r][0] = fmaf(am[r][kk], w.x, acc2[r][0]);
                        acc2[r][1] = fmaf(am[r][kk], w.y, acc2[r][1]);
                    }
                }
#pragma unroll
                for (int r = 0; r < 4; r++) av[r] = avn[r];
#pragma unroll
                for (int kk = 0; kk < 4; kk++) wv[kk] = wvn[kk];
            }
        }
        __syncthreads();    // W2c fully consumed

        // prefetch W2(ci+1) (overlaps next ff1)
        if (ci < 3) {
            const float* src = W2 + (c0 + 128) * DD;
#pragma unroll
            for (int i = 0; i < 16; i++) {
                int t16 = tid + i * 256;
                int k = t16 >> 5, c4 = (t16 & 31) << 2;
                cp_async16(w2s + (uint32_t)(k * DD + c4) * 4, src + k * DD + c4);
            }
            cp_commit();
        }
    }

    // epilogue: +b2 +residual (hs), LN (warp partial + 2-way combine)
    float v[4][2], s[4], q[4];
    float b20 = b2[c2], b21 = b2[c2 + 1];
#pragma unroll
    for (int r = 0; r < 4; r++) {
        v[r][0] = acc2[r][0] + b20 + hs[rg4 + r][c2];
        v[r][1] = acc2[r][1] + b21 + hs[rg4 + r][c2 + 1];
        s[r] = v[r][0] + v[r][1];
        q[r] = v[r][0] * v[r][0] + v[r][1] * v[r][1];
    }
#pragma unroll
    for (int o = 16; o > 0; o >>= 1)
#pragma unroll
        for (int r = 0; r < 4; r++) {
            s[r] += __shfl_xor_sync(0xffffffffu, s[r], o);
            q[r] += __shfl_xor_sync(0xffffffffu, q[r], o);
        }
    if (lane == 0)
#pragma unroll
        for (int r = 0; r < 4; r++) { lnS[cg][rg4 + r] = s[r]; lnQ[cg][rg4 + r] = q[r]; }
    __syncthreads();
    float g0 = gf[c2], g1 = gf[c2 + 1], e0 = bgf[c2], e1 = bgf[c2 + 1];
#pragma unroll
    for (int r = 0; r < 4; r++) {
        float S = lnS[0][rg4 + r] + lnS[1][rg4 + r];
        float Q = lnQ[0][rg4 + r] + lnQ[1][rg4 + r];
        float mean = S * (1.0f / DD);
        float rstd = rsqrtf(Q * (1.0f / DD) - mean * mean + LN_EPS);
        float2 o;
        o.x = (v[r][0] - mean) * rstd * g0 + e0;
        o.y = (v[r][1] - mean) * rstd * g1 + e1;
        int row = row0 + rg4 + r;
        if (FINAL) *reinterpret_cast<float2*>(&out[row * DD + c2]) = o;
        else       *reinterpret_cast<float2*>(&g_h[row * DD + c2]) = o;
    }
}

extern "C" void kernel_launch(void* const* d_in, const int* in_sizes, int n_in,
                              void* d_out, int out_size) {
    const float* x   = (const float*)d_in[0];   // (8,256,2)
    const float* We  = (const float*)d_in[1];   // (2,128)
    const float* be  = (const float*)d_in[2];
    const float* ge  = (const float*)d_in[3];
    const float* bge = (const float*)d_in[4];
    const float* Wp  = (const float*)d_in[5];   // (2,256,128)
    const float* bp  = (const float*)d_in[6];
    const float* gp  = (const float*)d_in[7];
    const float* bgp = (const float*)d_in[8];
    const float* W1  = (const float*)d_in[9];   // (2,128,512)
    const float* b1  = (const float*)d_in[10];
    const float* W2  = (const float*)d_in[11];  // (2,512,128)
    const float* b2  = (const float*)d_in[12];
    const float* gf  = (const float*)d_in[13];
    const float* bgf = (const float*)d_in[14];
    float* out = (float*)d_out;                 // (8,256,128) fp32

    cudaFuncSetAttribute(pool_kernel,
                         cudaFuncAttributeMaxDynamicSharedMemorySize, POOL_SMEM);
    cudaFuncSetAttribute(ff_fused_kernel<false>,
                         cudaFuncAttributeMaxDynamicSharedMemorySize, FF_SMEM);
    cudaFuncSetAttribute(ff_fused_kernel<true>,
                         cudaFuncAttributeMaxDynamicSharedMemorySize, FF_SMEM);

    embed_ln_kernel<<<T_TOK, 128>>>(x, We, be, ge, bge);

    for (int i = 0; i < 2; i++) {
        pool_kernel<<<T_TOK / 16, 256, POOL_SMEM>>>(
            Wp + i * 2 * DD * DD, bp + i * DD, gp + i * DD, bgp + i * DD);

        if (i == 1)
            ff_fused_kernel<true><<<T_TOK / 16, 256, FF_SMEM>>>(
                W1 + i * DD * HH, b1 + i * HH, W2 + i * HH * DD, b2 + i * DD,
                gf + i * DD, bgf + i * DD, out);
        else
            ff_fused_kernel<false><<<T_TOK / 16, 256, FF_SMEM>>>(
                W1 + i * DD * HH, b1 + i * HH, W2 + i * HH * DD, b2 + i * DD,
                gf + i * DD, bgf + i * DD, nullptr);
    }
}

// round 12
// speedup vs baseline: 1.7279x; 1.0191x over previous
#include <cuda_runtime.h>
#include <cstdint>

// PermutationInvariantNet: B=8, N=256, IN_DIM=2, D=128, H=512, L=2
// Tokens T = B*N = 2048. fp32.
// 7 launches: embed, 2x { stats, pool(K=128 gemm + common + corr + res + LN),
//                         ff(ff1+relu+ff2+res+LN) }.
// GEMM core (proven R6 economy): 256 thr = 8 warps (4 rowgrp x 2 colgrp),
// thread = 4 rows x 2 cols -> crossbar 32 wf/k == FFMA 32 cyc/k.
// Pool trick: pooled@Wb = m1@Wb (common to all tokens) + (m2-m1) corr at the
// <=16 argmax-owning rows of this block (hit list), so pool GEMM K=256 -> 128.

#define T_TOK 2048
#define NB 8
#define NN 256
#define DD 128
#define HH 512
#define LN_EPS 1e-5f
#define NEG_INF -3.402823466e38f

__device__ __align__(16) float g_h[T_TOK * DD];   // hidden state (1 MB)
__device__ float g_m1[NB * DD];                   // per-batch per-feature max
__device__ float g_m2[NB * DD];                   // second max
__device__ int   g_i1[NB * DD];                   // argmax (n within batch)

// -------- cp.async helpers --------
__device__ __forceinline__ void cp_async16(uint32_t dst, const void* src) {
    asm volatile("cp.async.cg.shared.global [%0], [%1], 16;" :: "r"(dst), "l"(src));
}
__device__ __forceinline__ void cp_commit() { asm volatile("cp.async.commit_group;"); }
__device__ __forceinline__ void cp_wait1()  { asm volatile("cp.async.wait_group 1;"); }
__device__ __forceinline__ void cp_wait0()  { asm volatile("cp.async.wait_group 0;"); }

// ===================== embed + LN =====================
__global__ void __launch_bounds__(128)
embed_ln_kernel(const float* __restrict__ x, const float* __restrict__ We,
                const float* __restrict__ be, const float* __restrict__ ge,
                const float* __restrict__ bge) {
    __shared__ float sh[8];
    int t = blockIdx.x, d = threadIdx.x;
    float x0 = x[t * 2 + 0];
    float x1 = x[t * 2 + 1];
    float y = fmaf(x0, We[d], fmaf(x1, We[DD + d], be[d]));
    float s = y, q = y * y;
#pragma unroll
    for (int o = 16; o > 0; o >>= 1) {
        s += __shfl_xor_sync(0xffffffffu, s, o);
        q += __shfl_xor_sync(0xffffffffu, q, o);
    }
    int lane = threadIdx.x & 31, w = threadIdx.x >> 5;
    if (lane == 0) { sh[w] = s; sh[4 + w] = q; }
    __syncthreads();
    s = sh[0] + sh[1] + sh[2] + sh[3];
    q = sh[4] + sh[5] + sh[6] + sh[7];
    float mean = s * (1.0f / DD);
    float rstd = rsqrtf(q * (1.0f / DD) - mean * mean + LN_EPS);
    g_h[t * DD + d] = (y - mean) * rstd * ge[d] + bge[d];
}

// ===================== per-batch (max1, max2, argmax) over N=256 ==========
__global__ void __launch_bounds__(512)
stats_kernel() {
    int b = blockIdx.x;
    int d = threadIdx.x;
    int s = threadIdx.y;
    const float* hb = g_h + b * NN * DD;

    float m1 = NEG_INF, m2 = NEG_INF;
    int i1 = 0;
    int n0 = s * (NN / 4);
#pragma unroll 8
    for (int n = n0; n < n0 + NN / 4; n++) {
        float v = hb[n * DD + d];
        if (v > m1) { m2 = m1; m1 = v; i1 = n; }
        else if (v > m2) { m2 = v; }
    }
    __shared__ float sm1[4][DD], sm2[4][DD];
    __shared__ int si1[4][DD];
    sm1[s][d] = m1; sm2[s][d] = m2; si1[s][d] = i1;
    __syncthreads();
    if (s == 0) {
#pragma unroll
        for (int j = 1; j < 4; j++) {
            float a1 = sm1[j][d], a2 = sm2[j][d];
            int ai = si1[j][d];
            if (a1 > m1) { m2 = fmaxf(m1, a2); m1 = a1; i1 = ai; }
            else         { m2 = fmaxf(m2, a1); }
        }
        g_m1[b * DD + d] = m1;
        g_m2[b * DD + d] = m2;
        g_i1[b * DD + d] = i1;
    }
}

// ===================== pool: K=128 GEMM + common + corr + res + LN =========
// h' = LN(h + h@Wt + [m1@Wb + sparse corr] + bp); in-place on g_h (each block
// reads/writes only its own 16 rows; stats come from the stats kernel).
// smem float offsets:
//   As 0 [16][128]=2048 | Ws 2048 [256][128]=32768 (Wt rows 0..127, Wb 128..255)
//   m1f 34816 [128] | m2f 34944 [128] | cpart 35072 [4][128]=512
//   lnS 35584 [2][16] | lnQ 35616 [2][16] | hitk 35648 [128] | hitl 35776 [128]
//   cnt 35904
#define POOL_SMEM (35908 * 4)
__global__ void __launch_bounds__(256, 1)
pool_kernel(const float* __restrict__ Wp, const float* __restrict__ bp,
            const float* __restrict__ gp, const float* __restrict__ bgp) {
    extern __shared__ float sm[];
    float (*As)[DD]    = reinterpret_cast<float (*)[DD]>(sm);
    float (*Ws)[DD]    = reinterpret_cast<float (*)[DD]>(sm + 2048);
    float* m1f         = sm + 34816;
    float* m2f         = sm + 34944;
    float (*cpart)[DD] = reinterpret_cast<float (*)[DD]>(sm + 35072);
    float (*lnS)[16]   = reinterpret_cast<float (*)[16]>(sm + 35584);
    float (*lnQ)[16]   = reinterpret_cast<float (*)[16]>(sm + 35616);
    int*   hitk        = reinterpret_cast<int*>(sm + 35648);
    int*   hitl        = reinterpret_cast<int*>(sm + 35776);
    int*   cnt         = reinterpret_cast<int*>(sm + 35904);

    const int tid = threadIdx.x;
    const int lane = tid & 31, wid = tid >> 5;
    const int rg = wid & 3, cg = wid >> 2;
    const int rg4 = rg * 4;
    const int c2 = cg * 64 + lane * 2;
    const int row0 = blockIdx.x * 16;
    const int b = row0 >> 8;
    const int nbase = row0 & 255;

    // --- issue Wp cp.async: rows 0..127 (Wt, group0), rows 128..255 (Wb, group1)
    uint32_t ws_base = (uint32_t)__cvta_generic_to_shared(&Ws[0][0]);
#pragma unroll
    for (int h = 0; h < 2; h++) {
#pragma unroll
        for (int i = 0; i < 16; i++) {
            int t16 = tid + i * 256;            // 0..4095 float4s
            int k = h * 128 + (t16 >> 5);
            int c4 = (t16 & 31) << 2;
            cp_async16(ws_base + (uint32_t)(k * DD + c4) * 4, Wp + k * DD + c4);
        }
        cp_commit();
    }

    if (tid == 0) *cnt = 0;

    // --- load A tile (16 tokens; also the residual) ---
#pragma unroll
    for (int i = 0; i < 2; i++) {
        int idx4 = (tid + i * 256) * 4;
        *reinterpret_cast<float4*>(&As[idx4 >> 7][idx4 & 127]) =
            *reinterpret_cast<const float4*>(&g_h[row0 * DD + idx4]);
    }
    __syncthreads();    // cnt reset visible before atomics

    // --- load stats + build hit list (threads 0..127, feature k = tid) ---
    if (tid < DD) {
        float m1 = g_m1[b * DD + tid];
        float m2 = g_m2[b * DD + tid];
        int i1 = g_i1[b * DD + tid];
        m1f[tid] = m1; m2f[tid] = m2;
        int l = i1 - nbase;
        if (l >= 0 && l < 16) {
            int idx = atomicAdd(cnt, 1);
            hitk[idx] = tid; hitl[idx] = l;
        }
    }

    float acc[4][2];
#pragma unroll
    for (int r = 0; r < 4; r++) { acc[r][0] = 0.f; acc[r][1] = 0.f; }

    cp_wait1();          // Wt ready
    __syncthreads();     // + As, stats, hit list visible

    // --- GEMM: acc = As(16x128) @ Wt(128x128), R6 core ---
#pragma unroll 4
    for (int k0 = 0; k0 < 128; k0 += 4) {
        float a[4][4];
#pragma unroll
        for (int r = 0; r < 4; r++)
            *reinterpret_cast<float4*>(a[r]) =
                *reinterpret_cast<const float4*>(&As[rg4 + r][k0]);
#pragma unroll
        for (int kk = 0; kk < 4; kk++) {
            float2 w = *reinterpret_cast<const float2*>(&Ws[k0 + kk][c2]);
#pragma unroll
            for (int r = 0; r < 4; r++) {
                acc[r][0] = fmaf(a[r][kk], w.x, acc[r][0]);
                acc[r][1] = fmaf(a[r][kk], w.y, acc[r][1]);
            }
        }
    }

    cp_wait0();          // Wb ready
    __syncthreads();

    // --- common = m1 @ Wb, k-split over the 4 rowgroups ---
    {
        float p0 = 0.f, p1 = 0.f;
        int kb = rg * 32;
#pragma unroll 8
        for (int k = kb; k < kb + 32; k++) {
            float m = m1f[k];
            float2 w = *reinterpret_cast<const float2*>(&Ws[128 + k][c2]);
            p0 = fmaf(m, w.x, p0);
            p1 = fmaf(m, w.y, p1);
        }
        cpart[rg][c2] = p0;
        cpart[rg][c2 + 1] = p1;
    }
    __syncthreads();

    // --- sparse correction: rows holding an argmax get (m2-m1)*Wb[k,:] ---
    float cr0[4] = {0.f, 0.f, 0.f, 0.f}, cr1[4] = {0.f, 0.f, 0.f, 0.f};
    int nh = *cnt;
    for (int j = 0; j < nh; j++) {
        int k = hitk[j], l = hitl[j];
        if ((l >> 2) == rg) {
            float dl = m2f[k] - m1f[k];
            float2 w = *reinterpret_cast<const float2*>(&Ws[128 + k][c2]);
            cr0[l & 3] = fmaf(dl, w.x, cr0[l & 3]);
            cr1[l & 3] = fmaf(dl, w.y, cr1[l & 3]);
        }
    }
    float common0 = cpart[0][c2] + cpart[1][c2] + cpart[2][c2] + cpart[3][c2];
    float common1 = cpart[0][c2 + 1] + cpart[1][c2 + 1] + cpart[2][c2 + 1] + cpart[3][c2 + 1];

    // --- epilogue: +bias +residual, LN (warp partial + 2-way combine) ---
    float v[4][2], s[4], q[4];
    float bp0 = bp[c2], bp1 = bp[c2 + 1];
#pragma unroll
    for (int r = 0; r < 4; r++) {
        v[r][0] = acc[r][0] + common0 + cr0[r] + bp0 + As[rg4 + r][c2];
        v[r][1] = acc[r][1] + common1 + cr1[r] + bp1 + As[rg4 + r][c2 + 1];
        s[r] = v[r][0] + v[r][1];
        q[r] = v[r][0] * v[r][0] + v[r][1] * v[r][1];
    }
#pragma unroll
    for (int o = 16; o > 0; o >>= 1)
#pragma unroll
        for (int r = 0; r < 4; r++) {
            s[r] += __shfl_xor_sync(0xffffffffu, s[r], o);
            q[r] += __shfl_xor_sync(0xffffffffu, q[r], o);
        }
    if (lane == 0)
#pragma unroll
        for (int r = 0; r < 4; r++) { lnS[cg][rg4 + r] = s[r]; lnQ[cg][rg4 + r] = q[r]; }
    __syncthreads();
    float g0 = gp[c2], g1 = gp[c2 + 1], e0 = bgp[c2], e1 = bgp[c2 + 1];
#pragma unroll
    for (int r = 0; r < 4; r++) {
        float S = lnS[0][rg4 + r] + lnS[1][rg4 + r];
        float Q = lnQ[0][rg4 + r] + lnQ[1][rg4 + r];
        float mean = S * (1.0f / DD);
        float rstd = rsqrtf(Q * (1.0f / DD) - mean * mean + LN_EPS);
        float2 o;
        o.x = (v[r][0] - mean) * rstd * g0 + e0;
        o.y = (v[r][1] - mean) * rstd * g1 + e1;
        *reinterpret_cast<float2*>(&g_h[(row0 + rg4 + r) * DD + c2]) = o;
    }
}

// ===================== fused FF (R6, unchanged) =====================
// h' = LN(h + relu(h@W1+b1)@W2 + b2). 4 H-chunks of 128.
// smem floats: hs[16][128]=2048 | W1c[2][128][128]=32768 | W2c[128][128]=16384
//              | Us[16][128]=2048 | lnS/Q 64
#define FF_SMEM ((2048 + 32768 + 16384 + 2048 + 64) * 4)
template <bool FINAL>
__global__ void __launch_bounds__(256, 1)
ff_fused_kernel(const float* __restrict__ W1, const float* __restrict__ b1,
                const float* __restrict__ W2, const float* __restrict__ b2,
                const float* __restrict__ gf, const float* __restrict__ bgf,
                float* __restrict__ out) {
    extern __shared__ float smem[];
    float (*hs)[DD]  = reinterpret_cast<float (*)[DD]>(smem);
    float* W1c       = smem + 2048;
    float (*W2c)[DD] = reinterpret_cast<float (*)[DD]>(smem + 2048 + 32768);
    float (*Us)[DD]  = reinterpret_cast<float (*)[DD]>(smem + 2048 + 32768 + 16384);
    float (*lnS)[16] = reinterpret_cast<float (*)[16]>(smem + 2048 + 32768 + 16384 + 2048);
    float (*lnQ)[16] = reinterpret_cast<float (*)[16]>(smem + 2048 + 32768 + 16384 + 2048 + 32);

    const int tid = threadIdx.x;
    const int lane = tid & 31, wid = tid >> 5;
    const int rg = wid & 3, cg = wid >> 2;
    const int rg4 = rg * 4;
    const int c2 = cg * 64 + lane * 2;
    const int row0 = blockIdx.x * 16;

    const uint32_t w1s = (uint32_t)__cvta_generic_to_shared(W1c);
    const uint32_t w2s = (uint32_t)__cvta_generic_to_shared(&W2c[0][0]);

    // chunk-0 weight loads
#pragma unroll
    for (int i = 0; i < 16; i++) {               // W1 chunk 0 -> buf 0
        int t16 = tid + i * 256;
        int k = t16 >> 5, c4 = (t16 & 31) << 2;
        cp_async16(w1s + (uint32_t)(k * DD + c4) * 4, W1 + k * HH + c4);
    }
    cp_commit();
#pragma unroll
    for (int i = 0; i < 16; i++) {               // W2 chunk 0
        int t16 = tid + i * 256;
        int k = t16 >> 5, c4 = (t16 & 31) << 2;
        cp_async16(w2s + (uint32_t)(k * DD + c4) * 4, W2 + k * DD + c4);
    }
    cp_commit();

    // load h rows (doubles as residual)
#pragma unroll
    for (int i = 0; i < 2; i++) {
        int idx4 = (tid + i * 256) * 4;
        *reinterpret_cast<float4*>(&hs[idx4 >> 7][idx4 & 127]) =
            *reinterpret_cast<const float4*>(&g_h[row0 * DD + idx4]);
    }

    float acc2[4][2];
#pragma unroll
    for (int r = 0; r < 4; r++) { acc2[r][0] = 0.f; acc2[r][1] = 0.f; }

    for (int ci = 0; ci < 4; ci++) {
        const int c0 = ci * 128;
        const float* W1b = W1c + (ci & 1) * 16384;

        cp_wait1();          // W1(ci) landed
        __syncthreads();     // + hs/Us hazards

        // ---- ff1: acc1 = hs @ W1b ----
        float acc1[4][2];
#pragma unroll
        for (int r = 0; r < 4; r++) { acc1[r][0] = 0.f; acc1[r][1] = 0.f; }
#pragma unroll 4
        for (int k0 = 0; k0 < 128; k0 += 4) {
            float a[4][4];
#pragma unroll
            for (int r = 0; r < 4; r++)
                *reinterpret_cast<float4*>(a[r]) =
                    *reinterpret_cast<const float4*>(&hs[rg4 + r][k0]);
#pragma unroll
            for (int kk = 0; kk < 4; kk++) {
                float2 w = *reinterpret_cast<const float2*>(&W1b[(k0 + kk) * DD + c2]);
#pragma unroll
                for (int r = 0; r < 4; r++) {
                    acc1[r][0] = fmaf(a[r][kk], w.x, acc1[r][0]);
                    acc1[r][1] = fmaf(a[r][kk], w.y, acc1[r][1]);
                }
            }
        }
        // Us = relu(acc1 + b1)
        {
            float bb0 = b1[c0 + c2], bb1 = b1[c0 + c2 + 1];
#pragma unroll
            for (int r = 0; r < 4; r++) {
                float2 u;
                u.x = fmaxf(acc1[r][0] + bb0, 0.0f);
                u.y = fmaxf(acc1[r][1] + bb1, 0.0f);
                *reinterpret_cast<float2*>(&Us[rg4 + r][c2]) = u;
            }
        }

        // prefetch W1(ci+1) into the other buffer (overlaps ff2)
        if (ci < 3) {
            uint32_t dst = w1s + (uint32_t)(((ci + 1) & 1) * 16384) * 4;
            const float* src = W1 + c0 + 128;
#pragma unroll
            for (int i = 0; i < 16; i++) {
                int t16 = tid + i * 256;
                int k = t16 >> 5, c4 = (t16 & 31) << 2;
                cp_async16(dst + (uint32_t)(k * DD + c4) * 4, src + k * HH + c4);
            }
            cp_commit();
        }

        if (ci < 3) cp_wait1(); else cp_wait0();   // W2(ci) landed
        __syncthreads();                            // + Us visible

        // ---- ff2 partial: acc2 += Us @ W2c ----
#pragma unroll 4
        for (int k0 = 0; k0 < 128; k0 += 4) {
            float a[4][4];
#pragma unroll
            for (int r = 0; r < 4; r++)
                *reinterpret_cast<float4*>(a[r]) =
                    *reinterpret_cast<const float4*>(&Us[rg4 + r][k0]);
#pragma unroll
            for (int kk = 0; kk < 4; kk++) {
                float2 w = *reinterpret_cast<const float2*>(&W2c[k0 + kk][c2]);
#pragma unroll
                for (int r = 0; r < 4; r++) {
                    acc2[r][0] = fmaf(a[r][kk], w.x, acc2[r][0]);
                    acc2[r][1] = fmaf(a[r][kk], w.y, acc2[r][1]);
                }
            }
        }
        __syncthreads();    // W2c fully consumed

        // prefetch W2(ci+1) (overlaps next ff1)
        if (ci < 3) {
            const float* src = W2 + (c0 + 128) * DD;
#pragma unroll
            for (int i = 0; i < 16; i++) {
                int t16 = tid + i * 256;
                int k = t16 >> 5, c4 = (t16 & 31) << 2;
                cp_async16(w2s + (uint32_t)(k * DD + c4) * 4, src + k * DD + c4);
            }
            cp_commit();
        }
    }

    // epilogue: +b2 +residual (hs), LN (warp partial + 2-way combine)
    float v[4][2], s[4], q[4];
    float b20 = b2[c2], b21 = b2[c2 + 1];
#pragma unroll
    for (int r = 0; r < 4; r++) {
        v[r][0] = acc2[r][0] + b20 + hs[rg4 + r][c2];
        v[r][1] = acc2[r][1] + b21 + hs[rg4 + r][c2 + 1];
        s[r] = v[r][0] + v[r][1];
        q[r] = v[r][0] * v[r][0] + v[r][1] * v[r][1];
    }
#pragma unroll
    for (int o = 16; o > 0; o >>= 1)
#pragma unroll
        for (int r = 0; r < 4; r++) {
            s[r] += __shfl_xor_sync(0xffffffffu, s[r], o);
            q[r] += __shfl_xor_sync(0xffffffffu, q[r], o);
        }
    if (lane == 0)
#pragma unroll
        for (int r = 0; r < 4; r++) { lnS[cg][rg4 + r] = s[r]; lnQ[cg][rg4 + r] = q[r]; }
    __syncthreads();
    float g0 = gf[c2], g1 = gf[c2 + 1], e0 = bgf[c2], e1 = bgf[c2 + 1];
#pragma unroll
    for (int r = 0; r < 4; r++) {
        float S = lnS[0][rg4 + r] + lnS[1][rg4 + r];
        float Q = lnQ[0][rg4 + r] + lnQ[1][rg4 + r];
        float mean = S * (1.0f / DD);
        float rstd = rsqrtf(Q * (1.0f / DD) - mean * mean + LN_EPS);
        float2 o;
        o.x = (v[r][0] - mean) * rstd * g0 + e0;
        o.y = (v[r][1] - mean) * rstd * g1 + e1;
        int row = row0 + rg4 + r;
        if (FINAL) *reinterpret_cast<float2*>(&out[row * DD + c2]) = o;
        else       *reinterpret_cast<float2*>(&g_h[row * DD + c2]) = o;
    }
}

extern "C" void kernel_launch(void* const* d_in, const int* in_sizes, int n_in,
                              void* d_out, int out_size) {
    const float* x   = (const float*)d_in[0];   // (8,256,2)
    const float* We  = (const float*)d_in[1];   // (2,128)
    const float* be  = (const float*)d_in[2];
    const float* ge  = (const float*)d_in[3];
    const float* bge = (const float*)d_in[4];
    const float* Wp  = (const float*)d_in[5];   // (2,256,128)
    const float* bp  = (const float*)d_in[6];
    const float* gp  = (const float*)d_in[7];
    const float* bgp = (const float*)d_in[8];
    const float* W1  = (const float*)d_in[9];   // (2,128,512)
    const float* b1  = (const float*)d_in[10];
    const float* W2  = (const float*)d_in[11];  // (2,512,128)
    const float* b2  = (const float*)d_in[12];
    const float* gf  = (const float*)d_in[13];
    const float* bgf = (const float*)d_in[14];
    float* out = (float*)d_out;                 // (8,256,128) fp32

    cudaFuncSetAttribute(pool_kernel,
                         cudaFuncAttributeMaxDynamicSharedMemorySize, POOL_SMEM);
    cudaFuncSetAttribute(ff_fused_kernel<false>,
                         cudaFuncAttributeMaxDynamicSharedMemorySize, FF_SMEM);
    cudaFuncSetAttribute(ff_fused_kernel<true>,
                         cudaFuncAttributeMaxDynamicSharedMemorySize, FF_SMEM);

    embed_ln_kernel<<<T_TOK, 128>>>(x, We, be, ge, bge);

    for (int i = 0; i < 2; i++) {
        stats_kernel<<<NB, dim3(128, 4)>>>();

        pool_kernel<<<T_TOK / 16, 256, POOL_SMEM>>>(
            Wp + i * 2 * DD * DD, bp + i * DD, gp + i * DD, bgp + i * DD);

        if (i == 1)
            ff_fused_kernel<true><<<T_TOK / 16, 256, FF_SMEM>>>(
                W1 + i * DD * HH, b1 + i * HH, W2 + i * HH * DD, b2 + i * DD,
                gf + i * DD, bgf + i * DD, out);
        else
            ff_fused_kernel<false><<<T_TOK / 16, 256, FF_SMEM>>>(
                W1 + i * DD * HH, b1 + i * HH, W2 + i * HH * DD, b2 + i * DD,
                gf + i * DD, bgf + i * DD, nullptr);
    }
}

// round 13
// speedup vs baseline: 1.8598x; 1.0764x over previous
#include <cuda_runtime.h>
#include <cstdint>

// PermutationInvariantNet: B=8, N=256, IN_DIM=2, D=128, H=512, L=2
// Tokens T = B*N = 2048. fp32.
// 7 launches: embed, 2x { stats, pool, ff }.
// GEMM economy (R6-proven, per warp): thread = 4 rows x 2 cols, float4-A
// broadcast + float2-W  ->  crossbar 96 wf/quad < FFMA 128 cyc/quad.
// NEW: k-group split — 512 threads = 2 kgroups covering half the k-range each,
// doubling warps/SMSP (2->4) at identical per-warp economy. Partials combine
// through smem.

#define T_TOK 2048
#define NB 8
#define NN 256
#define DD 128
#define HH 512
#define LN_EPS 1e-5f
#define NEG_INF -3.402823466e38f

__device__ __align__(16) float g_h[T_TOK * DD];   // hidden state (1 MB)
__device__ float g_m1[NB * DD];                   // per-batch per-feature max
__device__ float g_m2[NB * DD];                   // second max
__device__ int   g_i1[NB * DD];                   // argmax (n within batch)

// -------- cp.async helpers --------
__device__ __forceinline__ void cp_async16(uint32_t dst, const void* src) {
    asm volatile("cp.async.cg.shared.global [%0], [%1], 16;" :: "r"(dst), "l"(src));
}
__device__ __forceinline__ void cp_commit() { asm volatile("cp.async.commit_group;"); }
__device__ __forceinline__ void cp_wait1()  { asm volatile("cp.async.wait_group 1;"); }
__device__ __forceinline__ void cp_wait0()  { asm volatile("cp.async.wait_group 0;"); }
__device__ __forceinline__ void bar_sync(int id, int cnt) {
    asm volatile("bar.sync %0, %1;" :: "r"(id), "r"(cnt) : "memory");
}

// ===================== embed + LN =====================
__global__ void __launch_bounds__(128)
embed_ln_kernel(const float* __restrict__ x, const float* __restrict__ We,
                const float* __restrict__ be, const float* __restrict__ ge,
                const float* __restrict__ bge) {
    __shared__ float sh[8];
    int t = blockIdx.x, d = threadIdx.x;
    float x0 = x[t * 2 + 0];
    float x1 = x[t * 2 + 1];
    float y = fmaf(x0, We[d], fmaf(x1, We[DD + d], be[d]));
    float s = y, q = y * y;
#pragma unroll
    for (int o = 16; o > 0; o >>= 1) {
        s += __shfl_xor_sync(0xffffffffu, s, o);
        q += __shfl_xor_sync(0xffffffffu, q, o);
    }
    int lane = threadIdx.x & 31, w = threadIdx.x >> 5;
    if (lane == 0) { sh[w] = s; sh[4 + w] = q; }
    __syncthreads();
    s = sh[0] + sh[1] + sh[2] + sh[3];
    q = sh[4] + sh[5] + sh[6] + sh[7];
    float mean = s * (1.0f / DD);
    float rstd = rsqrtf(q * (1.0f / DD) - mean * mean + LN_EPS);
    g_h[t * DD + d] = (y - mean) * rstd * ge[d] + bge[d];
}

// ===================== per-batch (max1, max2, argmax) over N=256 ==========
__global__ void __launch_bounds__(512)
stats_kernel() {
    int b = blockIdx.x;
    int d = threadIdx.x;
    int s = threadIdx.y;
    const float* hb = g_h + b * NN * DD;

    float m1 = NEG_INF, m2 = NEG_INF;
    int i1 = 0;
    int n0 = s * (NN / 4);
#pragma unroll 8
    for (int n = n0; n < n0 + NN / 4; n++) {
        float v = hb[n * DD + d];
        if (v > m1) { m2 = m1; m1 = v; i1 = n; }
        else if (v > m2) { m2 = v; }
    }
    __shared__ float sm1[4][DD], sm2[4][DD];
    __shared__ int si1[4][DD];
    sm1[s][d] = m1; sm2[s][d] = m2; si1[s][d] = i1;
    __syncthreads();
    if (s == 0) {
#pragma unroll
        for (int j = 1; j < 4; j++) {
            float a1 = sm1[j][d], a2 = sm2[j][d];
            int ai = si1[j][d];
            if (a1 > m1) { m2 = fmaxf(m1, a2); m1 = a1; i1 = ai; }
            else         { m2 = fmaxf(m2, a1); }
        }
        g_m1[b * DD + d] = m1;
        g_m2[b * DD + d] = m2;
        g_i1[b * DD + d] = i1;
    }
}

// ===================== pool: h' = LN(h + [h, loo(h)] @ Wp + bp) ============
// In-place on g_h (block touches only its own 16 rows; stats precomputed).
// 512 thr = 2 kgroups of 256. kg0: loads Wt + As-h, GEMMs k 0..127.
// kg1: loads Wb + synthesizes pooled As, GEMMs k 128..255. Fully concurrent
// (per-kg cp groups, named barriers); one block-wide combine at the end.
// smem floats: As 0 [16][256]=4096 | Ws 4096 [256][128]=32768
//              | part 36864 [16][128]=2048 | lnS 38912 [2][16] | lnQ 38944
#define POOL_SMEM (38976 * 4)
__global__ void __launch_bounds__(512, 1)
pool_kernel(const float* __restrict__ Wp, const float* __restrict__ bp,
            const float* __restrict__ gp, const float* __restrict__ bgp) {
    extern __shared__ float sm[];
    float (*As)[256]   = reinterpret_cast<float (*)[256]>(sm);
    float (*Ws)[DD]    = reinterpret_cast<float (*)[DD]>(sm + 4096);
    float (*part)[DD]  = reinterpret_cast<float (*)[DD]>(sm + 36864);
    float (*lnS)[16]   = reinterpret_cast<float (*)[16]>(sm + 38912);
    float (*lnQ)[16]   = reinterpret_cast<float (*)[16]>(sm + 38944);

    const int tid = threadIdx.x;
    const int kg = tid >> 8;            // 0 or 1 (whole warps)
    const int t8 = tid & 255;
    const int lane = t8 & 31, wid8 = t8 >> 5;
    const int rg = wid8 & 3, cg = wid8 >> 2;
    const int rg4 = rg * 4;
    const int c2 = cg * 64 + lane * 2;
    const int row0 = blockIdx.x * 16;
    const int b = row0 >> 8;
    const int nbase = row0 & 255;

    uint32_t ws_base = (uint32_t)__cvta_generic_to_shared(&Ws[0][0]);

    float acc[4][2];
#pragma unroll
    for (int r = 0; r < 4; r++) { acc[r][0] = 0.f; acc[r][1] = 0.f; }

    if (kg == 0) {
        // --- kg0: issue Wt rows 0..127 (own cp group) ---
#pragma unroll
        for (int i = 0; i < 16; i++) {
            int t16 = t8 + i * 256;             // 0..4095 float4s
            int k = t16 >> 5, c4 = (t16 & 31) << 2;
            cp_async16(ws_base + (uint32_t)(k * DD + c4) * 4, Wp + k * DD + c4);
        }
        cp_commit();
        // --- As h-part (cols 0..127): 2 float4 per thread ---
#pragma unroll
        for (int i = 0; i < 2; i++) {
            int idx4 = (t8 + i * 256) * 4;      // 0..2044
            int r = idx4 >> 7, k = idx4 & 127;
            *reinterpret_cast<float4*>(&As[r][k]) =
                *reinterpret_cast<const float4*>(&g_h[row0 * DD + idx4]);
        }
        cp_wait0();                              // Wt landed (only own group)
        bar_sync(1, 256);                        // kg0-local: As-h + Wt visible
        // --- GEMM k 0..127 ---
#pragma unroll 4
        for (int k0 = 0; k0 < 128; k0 += 4) {
            float a[4][4];
#pragma unroll
            for (int r = 0; r < 4; r++)
                *reinterpret_cast<float4*>(a[r]) =
                    *reinterpret_cast<const float4*>(&As[rg4 + r][k0]);
#pragma unroll
            for (int kk = 0; kk < 4; kk++) {
                float2 w = *reinterpret_cast<const float2*>(&Ws[k0 + kk][c2]);
#pragma unroll
                for (int r = 0; r < 4; r++) {
                    acc[r][0] = fmaf(a[r][kk], w.x, acc[r][0]);
                    acc[r][1] = fmaf(a[r][kk], w.y, acc[r][1]);
                }
            }
        }
    } else {
        // --- kg1: issue Wb rows 128..255 (own cp group) ---
        const float* Wbot = Wp + DD * DD;
#pragma unroll
        for (int i = 0; i < 16; i++) {
            int t16 = t8 + i * 256;
            int k = t16 >> 5, c4 = (t16 & 31) << 2;
            cp_async16(ws_base + (uint32_t)((128 + k) * DD + c4) * 4,
                       Wbot + k * DD + c4);
        }
        cp_commit();
        // --- As pooled part (cols 128..255): 8 elems per thread ---
#pragma unroll
        for (int i = 0; i < 8; i++) {
            int idx = t8 + i * 256;             // 0..2047
            int r = idx >> 7, k = idx & 127;
            int am = g_i1[b * DD + k];
            float m1 = g_m1[b * DD + k], m2 = g_m2[b * DD + k];
            As[r][128 + k] = (nbase + r == am) ? m2 : m1;
        }
        cp_wait0();                              // Wb landed
        bar_sync(2, 256);                        // kg1-local
        // --- GEMM k 128..255 ---
#pragma unroll 4
        for (int k0 = 128; k0 < 256; k0 += 4) {
            float a[4][4];
#pragma unroll
            for (int r = 0; r < 4; r++)
                *reinterpret_cast<float4*>(a[r]) =
                    *reinterpret_cast<const float4*>(&As[rg4 + r][k0]);
#pragma unroll
            for (int kk = 0; kk < 4; kk++) {
                float2 w = *reinterpret_cast<const float2*>(&Ws[k0 + kk][c2]);
#pragma unroll
                for (int r = 0; r < 4; r++) {
                    acc[r][0] = fmaf(a[r][kk], w.x, acc[r][0]);
                    acc[r][1] = fmaf(a[r][kk], w.y, acc[r][1]);
                }
            }
        }
        // publish kg1 partials
#pragma unroll
        for (int r = 0; r < 4; r++) {
            part[rg4 + r][c2] = acc[r][0];
            part[rg4 + r][c2 + 1] = acc[r][1];
        }
    }
    __syncthreads();    // kg1 partials + kg0 As-h visible

    // --- epilogue (kg0 only): combine + bias + residual + LN ---
    if (kg == 0) {
        float v[4][2], s[4], q[4];
        float bp0 = bp[c2], bp1 = bp[c2 + 1];
#pragma unroll
        for (int r = 0; r < 4; r++) {
            v[r][0] = acc[r][0] + part[rg4 + r][c2] + bp0 + As[rg4 + r][c2];
            v[r][1] = acc[r][1] + part[rg4 + r][c2 + 1] + bp1 + As[rg4 + r][c2 + 1];
            s[r] = v[r][0] + v[r][1];
            q[r] = v[r][0] * v[r][0] + v[r][1] * v[r][1];
        }
#pragma unroll
        for (int o = 16; o > 0; o >>= 1)
#pragma unroll
            for (int r = 0; r < 4; r++) {
                s[r] += __shfl_xor_sync(0xffffffffu, s[r], o);
                q[r] += __shfl_xor_sync(0xffffffffu, q[r], o);
            }
        if (lane == 0)
#pragma unroll
            for (int r = 0; r < 4; r++) { lnS[cg][rg4 + r] = s[r]; lnQ[cg][rg4 + r] = q[r]; }
        bar_sync(1, 256);
        float g0 = gp[c2], g1 = gp[c2 + 1], e0 = bgp[c2], e1 = bgp[c2 + 1];
#pragma unroll
        for (int r = 0; r < 4; r++) {
            float S = lnS[0][rg4 + r] + lnS[1][rg4 + r];
            float Q = lnQ[0][rg4 + r] + lnQ[1][rg4 + r];
            float mean = S * (1.0f / DD);
            float rstd = rsqrtf(Q * (1.0f / DD) - mean * mean + LN_EPS);
            float2 o;
            o.x = (v[r][0] - mean) * rstd * g0 + e0;
            o.y = (v[r][1] - mean) * rstd * g1 + e1;
            *reinterpret_cast<float2*>(&g_h[(row0 + rg4 + r) * DD + c2]) = o;
        }
    }
}

// ===================== fused FF =====================
// h' = LN(h + relu(h@W1+b1)@W2 + b2). 4 H-chunks of 128, W1 double-buffered.
// 512 thr = 2 kgroups: each GEMM stage's k-range split in half across kgs;
// ff1 partials combined elementwise (with bias+relu), acc2 combined in epilogue.
// smem floats: hs 0 [16][128] | W1c 2048 [2][128][128] | W2c 34816 [128][128]
//              | Usp0 51200 [16][128] | Usp1 53248 [16][128]
//              | lnS 55296 [2][16] | lnQ 55328 [2][16]
#define FF_SMEM (55360 * 4)
template <bool FINAL>
__global__ void __launch_bounds__(512, 1)
ff_fused_kernel(const float* __restrict__ W1, const float* __restrict__ b1,
                const float* __restrict__ W2, const float* __restrict__ b2,
                const float* __restrict__ gf, const float* __restrict__ bgf,
                float* __restrict__ out) {
    extern __shared__ float sm[];
    float (*hs)[DD]   = reinterpret_cast<float (*)[DD]>(sm);
    float* W1c        = sm + 2048;
    float (*W2c)[DD]  = reinterpret_cast<float (*)[DD]>(sm + 34816);
    float (*Us)[DD]   = reinterpret_cast<float (*)[DD]>(sm + 51200);   // Usp0
    float (*Usp1)[DD] = reinterpret_cast<float (*)[DD]>(sm + 53248);
    float (*lnS)[16]  = reinterpret_cast<float (*)[16]>(sm + 55296);
    float (*lnQ)[16]  = reinterpret_cast<float (*)[16]>(sm + 55328);

    const int tid = threadIdx.x;
    const int kg = tid >> 8;            // 0/1, whole warps
    const int t8 = tid & 255;
    const int lane = t8 & 31, wid8 = t8 >> 5;
    const int rg = wid8 & 3, cg = wid8 >> 2;
    const int rg4 = rg * 4;
    const int c2 = cg * 64 + lane * 2;
    const int kb = kg * 64;             // this kgroup's k-offset within a 128 range
    const int row0 = blockIdx.x * 16;

    const uint32_t w1s = (uint32_t)__cvta_generic_to_shared(W1c);
    const uint32_t w2s = (uint32_t)__cvta_generic_to_shared(&W2c[0][0]);

    // chunk-0 weight loads (all 512 threads, 8 float4 each per buffer)
#pragma unroll
    for (int i = 0; i < 8; i++) {
        int t16 = tid + i * 512;
        int k = t16 >> 5, c4 = (t16 & 31) << 2;
        cp_async16(w1s + (uint32_t)(k * DD + c4) * 4, W1 + k * HH + c4);
    }
    cp_commit();
#pragma unroll
    for (int i = 0; i < 8; i++) {
        int t16 = tid + i * 512;
        int k = t16 >> 5, c4 = (t16 & 31) << 2;
        cp_async16(w2s + (uint32_t)(k * DD + c4) * 4, W2 + k * DD + c4);
    }
    cp_commit();

    // load h rows (doubles as residual): 1 float4 per thread
    {
        int idx4 = tid * 4;
        *reinterpret_cast<float4*>(&hs[idx4 >> 7][idx4 & 127]) =
            *reinterpret_cast<const float4*>(&g_h[row0 * DD + idx4]);
    }

    float acc2[4][2];
#pragma unroll
    for (int r = 0; r < 4; r++) { acc2[r][0] = 0.f; acc2[r][1] = 0.f; }

    for (int ci = 0; ci < 4; ci++) {
        const int c0 = ci * 128;
        const float* W1b = W1c + (ci & 1) * 16384;

        cp_wait1();          // W1(ci) landed
        __syncthreads();     // + hs / Usp / buffer hazards

        // ---- ff1 partial: k in [kb, kb+64) ----
        float acc1[4][2];
#pragma unroll
        for (int r = 0; r < 4; r++) { acc1[r][0] = 0.f; acc1[r][1] = 0.f; }
#pragma unroll 4
        for (int k0 = kb; k0 < kb + 64; k0 += 4) {
            float a[4][4];
#pragma unroll
            for (int r = 0; r < 4; r++)
                *reinterpret_cast<float4*>(a[r]) =
                    *reinterpret_cast<const float4*>(&hs[rg4 + r][k0]);
#pragma unroll
            for (int kk = 0; kk < 4; kk++) {
                float2 w = *reinterpret_cast<const float2*>(&W1b[(k0 + kk) * DD + c2]);
#pragma unroll
                for (int r = 0; r < 4; r++) {
                    acc1[r][0] = fmaf(a[r][kk], w.x, acc1[r][0]);
                    acc1[r][1] = fmaf(a[r][kk], w.y, acc1[r][1]);
                }
            }
        }
        // publish raw partials
        {
            float (*Up)[DD] = kg ? Usp1 : Us;
#pragma unroll
            for (int r = 0; r < 4; r++) {
                float2 u;
                u.x = acc1[r][0];
                u.y = acc1[r][1];
                *reinterpret_cast<float2*>(&Up[rg4 + r][c2]) = u;
            }
        }
        __syncthreads();

        // ---- combine: Us = relu(Usp0 + Usp1 + b1), elementwise in place ----
        {
            int idx4 = tid * 4;
            int r = idx4 >> 7, cc = idx4 & 127;
            float4 ua = *reinterpret_cast<const float4*>(&Us[r][cc]);
            float4 ub = *reinterpret_cast<const float4*>(&Usp1[r][cc]);
            float4 bb = *reinterpret_cast<const float4*>(&b1[c0 + cc]);
            float4 u;
            u.x = fmaxf(ua.x + ub.x + bb.x, 0.0f);
            u.y = fmaxf(ua.y + ub.y + bb.y, 0.0f);
            u.z = fmaxf(ua.z + ub.z + bb.z, 0.0f);
            u.w = fmaxf(ua.w + ub.w + bb.w, 0.0f);
            *reinterpret_cast<float4*>(&Us[r][cc]) = u;
        }

        // prefetch W1(ci+1) into the other buffer (overlaps ff2)
        if (ci < 3) {
            uint32_t dst = w1s + (uint32_t)(((ci + 1) & 1) * 16384) * 4;
            const float* src = W1 + c0 + 128;
#pragma unroll
            for (int i = 0; i < 8; i++) {
                int t16 = tid + i * 512;
                int k = t16 >> 5, c4 = (t16 & 31) << 2;
                cp_async16(dst + (uint32_t)(k * DD + c4) * 4, src + k * HH + c4);
            }
            cp_commit();
        }

        if (ci < 3) cp_wait1(); else cp_wait0();   // W2(ci) landed
        __syncthreads();                            // + Us final visible

        // ---- ff2 partial: acc2 += Us @ W2c over k in [kb, kb+64) ----
#pragma unroll 4
        for (int k0 = kb; k0 < kb + 64; k0 += 4) {
            float a[4][4];
#pragma unroll
            for (int r = 0; r < 4; r++)
                *reinterpret_cast<float4*>(a[r]) =
                    *reinterpret_cast<const float4*>(&Us[rg4 + r][k0]);
#pragma unroll
            for (int kk = 0; kk < 4; kk++) {
                float2 w = *reinterpret_cast<const float2*>(&W2c[k0 + kk][c2]);
#pragma unroll
                for (int r = 0; r < 4; r++) {
                    acc2[r][0] = fmaf(a[r][kk], w.x, acc2[r][0]);
                    acc2[r][1] = fmaf(a[r][kk], w.y, acc2[r][1]);
                }
            }
        }
        __syncthreads();    // W2c + Us fully consumed

        // prefetch W2(ci+1) (overlaps next ff1)
        if (ci < 3) {
            const float* src = W2 + (c0 + 128) * DD;
#pragma unroll
            for (int i = 0; i < 8; i++) {
                int t16 = tid + i * 512;
                int k = t16 >> 5, c4 = (t16 & 31) << 2;
                cp_async16(w2s + (uint32_t)(k * DD + c4) * 4, src + k * DD + c4);
            }
            cp_commit();
        }
    }

    // ---- epilogue: combine kg partials, +b2 +residual, LN (kg0 only) ----
    if (kg == 1) {
#pragma unroll
        for (int r = 0; r < 4; r++) {
            float2 u;
            u.x = acc2[r][0];
            u.y = acc2[r][1];
            *reinterpret_cast<float2*>(&Usp1[rg4 + r][c2]) = u;
        }
    }
    __syncthreads();

    if (kg == 0) {
        float v[4][2], s[4], q[4];
        float b20 = b2[c2], b21 = b2[c2 + 1];
#pragma unroll
        for (int r = 0; r < 4; r++) {
            v[r][0] = acc2[r][0] + Usp1[rg4 + r][c2] + b20 + hs[rg4 + r][c2];
            v[r][1] = acc2[r][1] + Usp1[rg4 + r][c2 + 1] + b21 + hs[rg4 + r][c2 + 1];
            s[r] = v[r][0] + v[r][1];
            q[r] = v[r][0] * v[r][0] + v[r][1] * v[r][1];
        }
#pragma unroll
        for (int o = 16; o > 0; o >>= 1)
#pragma unroll
            for (int r = 0; r < 4; r++) {
                s[r] += __shfl_xor_sync(0xffffffffu, s[r], o);
                q[r] += __shfl_xor_sync(0xffffffffu, q[r], o);
            }
        if (lane == 0)
#pragma unroll
            for (int r = 0; r < 4; r++) { lnS[cg][rg4 + r] = s[r]; lnQ[cg][rg4 + r] = q[r]; }
        bar_sync(1, 256);
        float g0 = gf[c2], g1 = gf[c2 + 1], e0 = bgf[c2], e1 = bgf[c2 + 1];
#pragma unroll
        for (int r = 0; r < 4; r++) {
            float S = lnS[0][rg4 + r] + lnS[1][rg4 + r];
            float Q = lnQ[0][rg4 + r] + lnQ[1][rg4 + r];
            float mean = S * (1.0f / DD);
            float rstd = rsqrtf(Q * (1.0f / DD) - mean * mean + LN_EPS);
            float2 o;
            o.x = (v[r][0] - mean) * rstd * g0 + e0;
            o.y = (v[r][1] - mean) * rstd * g1 + e1;
            int row = row0 + rg4 + r;
            if (FINAL) *reinterpret_cast<float2*>(&out[row * DD + c2]) = o;
            else       *reinterpret_cast<float2*>(&g_h[row * DD + c2]) = o;
        }
    }
}

extern "C" void kernel_launch(void* const* d_in, const int* in_sizes, int n_in,
                              void* d_out, int out_size) {
    const float* x   = (const float*)d_in[0];   // (8,256,2)
    const float* We  = (const float*)d_in[1];   // (2,128)
    const float* be  = (const float*)d_in[2];
    const float* ge  = (const float*)d_in[3];
    const float* bge = (const float*)d_in[4];
    const float* Wp  = (const float*)d_in[5];   // (2,256,128)
    const float* bp  = (const float*)d_in[6];
    const float* gp  = (const float*)d_in[7];
    const float* bgp = (const float*)d_in[8];
    const float* W1  = (const float*)d_in[9];   // (2,128,512)
    const float* b1  = (const float*)d_in[10];
    const float* W2  = (const float*)d_in[11];  // (2,512,128)
    const float* b2  = (const float*)d_in[12];
    const float* gf  = (const float*)d_in[13];
    const float* bgf = (const float*)d_in[14];
    float* out = (float*)d_out;                 // (8,256,128) fp32

    cudaFuncSetAttribute(pool_kernel,
                         cudaFuncAttributeMaxDynamicSharedMemorySize, POOL_SMEM);
    cudaFuncSetAttribute(ff_fused_kernel<false>,
                         cudaFuncAttributeMaxDynamicSharedMemorySize, FF_SMEM);
    cudaFuncSetAttribute(ff_fused_kernel<true>,
                         cudaFuncAttributeMaxDynamicSharedMemorySize, FF_SMEM);

    embed_ln_kernel<<<T_TOK, 128>>>(x, We, be, ge, bge);

    for (int i = 0; i < 2; i++) {
        stats_kernel<<<NB, dim3(128, 4)>>>();

        pool_kernel<<<T_TOK / 16, 512, POOL_SMEM>>>(
            Wp + i * 2 * DD * DD, bp + i * DD, gp + i * DD, bgp + i * DD);

        if (i == 1)
            ff_fused_kernel<true><<<T_TOK / 16, 512, FF_SMEM>>>(
                W1 + i * DD * HH, b1 + i * HH, W2 + i * HH * DD, b2 + i * DD,
                gf + i * DD, bgf + i * DD, out);
        else
            ff_fused_kernel<false><<<T_TOK / 16, 512, FF_SMEM>>>(
                W1 + i * DD * HH, b1 + i * HH, W2 + i * HH * DD, b2 + i * DD,
                gf + i * DD, bgf + i * DD, nullptr);
    }
}

// round 14
// speedup vs baseline: 1.9628x; 1.0554x over previous
#include <cuda_runtime.h>
#include <cstdint>

// PermutationInvariantNet: B=8, N=256, IN_DIM=2, D=128, H=512, L=2
// Tokens T = B*N = 2048. fp32.
// 7 launches: embed, 2x { stats, pool, ff }.
// ff core NEW: 256 thr = 8 warps = 2rg x 2cg x 2kg, thread = 8 rows x 2 cols.
//   Per warp per k: A 2wf + W 2wf = 4wf per 16 FFMA -> per-SM crossbar
//   32 cyc/k == FFMA 32 cyc/k (was 48 vs 32 crossbar-bound at rpt=4).
// pool: R13 concurrent-halves version (proven).

#define T_TOK 2048
#define NB 8
#define NN 256
#define DD 128
#define HH 512
#define LN_EPS 1e-5f
#define NEG_INF -3.402823466e38f

__device__ __align__(16) float g_h[T_TOK * DD];   // hidden state (1 MB)
__device__ float g_m1[NB * DD];                   // per-batch per-feature max
__device__ float g_m2[NB * DD];                   // second max
__device__ int   g_i1[NB * DD];                   // argmax (n within batch)

// -------- cp.async helpers --------
__device__ __forceinline__ void cp_async16(uint32_t dst, const void* src) {
    asm volatile("cp.async.cg.shared.global [%0], [%1], 16;" :: "r"(dst), "l"(src));
}
__device__ __forceinline__ void cp_commit() { asm volatile("cp.async.commit_group;"); }
__device__ __forceinline__ void cp_wait1()  { asm volatile("cp.async.wait_group 1;"); }
__device__ __forceinline__ void cp_wait0()  { asm volatile("cp.async.wait_group 0;"); }
__device__ __forceinline__ void bar_sync(int id, int cnt) {
    asm volatile("bar.sync %0, %1;" :: "r"(id), "r"(cnt) : "memory");
}

// ===================== embed + LN =====================
__global__ void __launch_bounds__(128)
embed_ln_kernel(const float* __restrict__ x, const float* __restrict__ We,
                const float* __restrict__ be, const float* __restrict__ ge,
                const float* __restrict__ bge) {
    __shared__ float sh[8];
    int t = blockIdx.x, d = threadIdx.x;
    float x0 = x[t * 2 + 0];
    float x1 = x[t * 2 + 1];
    float y = fmaf(x0, We[d], fmaf(x1, We[DD + d], be[d]));
    float s = y, q = y * y;
#pragma unroll
    for (int o = 16; o > 0; o >>= 1) {
        s += __shfl_xor_sync(0xffffffffu, s, o);
        q += __shfl_xor_sync(0xffffffffu, q, o);
    }
    int lane = threadIdx.x & 31, w = threadIdx.x >> 5;
    if (lane == 0) { sh[w] = s; sh[4 + w] = q; }
    __syncthreads();
    s = sh[0] + sh[1] + sh[2] + sh[3];
    q = sh[4] + sh[5] + sh[6] + sh[7];
    float mean = s * (1.0f / DD);
    float rstd = rsqrtf(q * (1.0f / DD) - mean * mean + LN_EPS);
    g_h[t * DD + d] = (y - mean) * rstd * ge[d] + bge[d];
}

// ===================== per-batch (max1, max2, argmax) over N=256 ==========
__global__ void __launch_bounds__(512)
stats_kernel() {
    int b = blockIdx.x;
    int d = threadIdx.x;
    int s = threadIdx.y;
    const float* hb = g_h + b * NN * DD;

    float m1 = NEG_INF, m2 = NEG_INF;
    int i1 = 0;
    int n0 = s * (NN / 4);
#pragma unroll 8
    for (int n = n0; n < n0 + NN / 4; n++) {
        float v = hb[n * DD + d];
        if (v > m1) { m2 = m1; m1 = v; i1 = n; }
        else if (v > m2) { m2 = v; }
    }
    __shared__ float sm1[4][DD], sm2[4][DD];
    __shared__ int si1[4][DD];
    sm1[s][d] = m1; sm2[s][d] = m2; si1[s][d] = i1;
    __syncthreads();
    if (s == 0) {
#pragma unroll
        for (int j = 1; j < 4; j++) {
            float a1 = sm1[j][d], a2 = sm2[j][d];
            int ai = si1[j][d];
            if (a1 > m1) { m2 = fmaxf(m1, a2); m1 = a1; i1 = ai; }
            else         { m2 = fmaxf(m2, a1); }
        }
        g_m1[b * DD + d] = m1;
        g_m2[b * DD + d] = m2;
        g_i1[b * DD + d] = i1;
    }
}

// ===================== pool (R13, proven): concurrent kgroup halves ========
// h' = LN(h + [h, loo(h)] @ Wp + bp); in-place on g_h.
// smem floats: As 0 [16][256]=4096 | Ws 4096 [256][128]=32768
//              | part 36864 [16][128]=2048 | lnS 38912 [2][16] | lnQ 38944
#define POOL_SMEM (38976 * 4)
__global__ void __launch_bounds__(512, 1)
pool_kernel(const float* __restrict__ Wp, const float* __restrict__ bp,
            const float* __restrict__ gp, const float* __restrict__ bgp) {
    extern __shared__ float sm[];
    float (*As)[256]   = reinterpret_cast<float (*)[256]>(sm);
    float (*Ws)[DD]    = reinterpret_cast<float (*)[DD]>(sm + 4096);
    float (*part)[DD]  = reinterpret_cast<float (*)[DD]>(sm + 36864);
    float (*lnS)[16]   = reinterpret_cast<float (*)[16]>(sm + 38912);
    float (*lnQ)[16]   = reinterpret_cast<float (*)[16]>(sm + 38944);

    const int tid = threadIdx.x;
    const int kg = tid >> 8;            // 0 or 1 (whole warps)
    const int t8 = tid & 255;
    const int lane = t8 & 31, wid8 = t8 >> 5;
    const int rg = wid8 & 3, cg = wid8 >> 2;
    const int rg4 = rg * 4;
    const int c2 = cg * 64 + lane * 2;
    const int row0 = blockIdx.x * 16;
    const int b = row0 >> 8;
    const int nbase = row0 & 255;

    uint32_t ws_base = (uint32_t)__cvta_generic_to_shared(&Ws[0][0]);

    float acc[4][2];
#pragma unroll
    for (int r = 0; r < 4; r++) { acc[r][0] = 0.f; acc[r][1] = 0.f; }

    if (kg == 0) {
#pragma unroll
        for (int i = 0; i < 16; i++) {
            int t16 = t8 + i * 256;
            int k = t16 >> 5, c4 = (t16 & 31) << 2;
            cp_async16(ws_base + (uint32_t)(k * DD + c4) * 4, Wp + k * DD + c4);
        }
        cp_commit();
#pragma unroll
        for (int i = 0; i < 2; i++) {
            int idx4 = (t8 + i * 256) * 4;
            int r = idx4 >> 7, k = idx4 & 127;
            *reinterpret_cast<float4*>(&As[r][k]) =
                *reinterpret_cast<const float4*>(&g_h[row0 * DD + idx4]);
        }
        cp_wait0();
        bar_sync(1, 256);
#pragma unroll 4
        for (int k0 = 0; k0 < 128; k0 += 4) {
            float a[4][4];
#pragma unroll
            for (int r = 0; r < 4; r++)
                *reinterpret_cast<float4*>(a[r]) =
                    *reinterpret_cast<const float4*>(&As[rg4 + r][k0]);
#pragma unroll
            for (int kk = 0; kk < 4; kk++) {
                float2 w = *reinterpret_cast<const float2*>(&Ws[k0 + kk][c2]);
#pragma unroll
                for (int r = 0; r < 4; r++) {
                    acc[r][0] = fmaf(a[r][kk], w.x, acc[r][0]);
                    acc[r][1] = fmaf(a[r][kk], w.y, acc[r][1]);
                }
            }
        }
    } else {
        const float* Wbot = Wp + DD * DD;
#pragma unroll
        for (int i = 0; i < 16; i++) {
            int t16 = t8 + i * 256;
            int k = t16 >> 5, c4 = (t16 & 31) << 2;
            cp_async16(ws_base + (uint32_t)((128 + k) * DD + c4) * 4,
                       Wbot + k * DD + c4);
        }
        cp_commit();
#pragma unroll
        for (int i = 0; i < 8; i++) {
            int idx = t8 + i * 256;
            int r = idx >> 7, k = idx & 127;
            int am = g_i1[b * DD + k];
            float m1 = g_m1[b * DD + k], m2 = g_m2[b * DD + k];
            As[r][128 + k] = (nbase + r == am) ? m2 : m1;
        }
        cp_wait0();
        bar_sync(2, 256);
#pragma unroll 4
        for (int k0 = 128; k0 < 256; k0 += 4) {
            float a[4][4];
#pragma unroll
            for (int r = 0; r < 4; r++)
                *reinterpret_cast<float4*>(a[r]) =
                    *reinterpret_cast<const float4*>(&As[rg4 + r][k0]);
#pragma unroll
            for (int kk = 0; kk < 4; kk++) {
                float2 w = *reinterpret_cast<const float2*>(&Ws[k0 + kk][c2]);
#pragma unroll
                for (int r = 0; r < 4; r++) {
                    acc[r][0] = fmaf(a[r][kk], w.x, acc[r][0]);
                    acc[r][1] = fmaf(a[r][kk], w.y, acc[r][1]);
                }
            }
        }
#pragma unroll
        for (int r = 0; r < 4; r++) {
            part[rg4 + r][c2] = acc[r][0];
            part[rg4 + r][c2 + 1] = acc[r][1];
        }
    }
    __syncthreads();

    if (kg == 0) {
        float v[4][2], s[4], q[4];
        float bp0 = bp[c2], bp1 = bp[c2 + 1];
#pragma unroll
        for (int r = 0; r < 4; r++) {
            v[r][0] = acc[r][0] + part[rg4 + r][c2] + bp0 + As[rg4 + r][c2];
            v[r][1] = acc[r][1] + part[rg4 + r][c2 + 1] + bp1 + As[rg4 + r][c2 + 1];
            s[r] = v[r][0] + v[r][1];
            q[r] = v[r][0] * v[r][0] + v[r][1] * v[r][1];
        }
#pragma unroll
        for (int o = 16; o > 0; o >>= 1)
#pragma unroll
            for (int r = 0; r < 4; r++) {
                s[r] += __shfl_xor_sync(0xffffffffu, s[r], o);
                q[r] += __shfl_xor_sync(0xffffffffu, q[r], o);
            }
        if (lane == 0)
#pragma unroll
            for (int r = 0; r < 4; r++) { lnS[cg][rg4 + r] = s[r]; lnQ[cg][rg4 + r] = q[r]; }
        bar_sync(1, 256);
        float g0 = gp[c2], g1 = gp[c2 + 1], e0 = bgp[c2], e1 = bgp[c2 + 1];
#pragma unroll
        for (int r = 0; r < 4; r++) {
            float S = lnS[0][rg4 + r] + lnS[1][rg4 + r];
            float Q = lnQ[0][rg4 + r] + lnQ[1][rg4 + r];
            float mean = S * (1.0f / DD);
            float rstd = rsqrtf(Q * (1.0f / DD) - mean * mean + LN_EPS);
            float2 o;
            o.x = (v[r][0] - mean) * rstd * g0 + e0;
            o.y = (v[r][1] - mean) * rstd * g1 + e1;
            *reinterpret_cast<float2*>(&g_h[(row0 + rg4 + r) * DD + c2]) = o;
        }
    }
}

// ===================== fused FF (rpt=8 crossbar-balanced core) =============
// h' = LN(h + relu(h@W1+b1)@W2 + b2). 4 H-chunks of 128, W1 double-buffered.
// 256 thr = 8 warps = 2rg x 2cg x 2kg; thread = 8 rows x 2 cols, k split
// across kgs; ff1 partials combined elementwise, acc2 combined in epilogue.
// smem floats: hs 0 [16][128] | W1c 2048 [2][128][128] | W2c 34816 [128][128]
//              | Usp0 51200 [16][128] | Usp1 53248 [16][128]
//              | lnS 55296 [2][16] | lnQ 55328 [2][16]
#define FF_SMEM (55360 * 4)
template <bool FINAL>
__global__ void __launch_bounds__(256, 1)
ff_fused_kernel(const float* __restrict__ W1, const float* __restrict__ b1,
                const float* __restrict__ W2, const float* __restrict__ b2,
                const float* __restrict__ gf, const float* __restrict__ bgf,
                float* __restrict__ out) {
    extern __shared__ float sm[];
    float (*hs)[DD]   = reinterpret_cast<float (*)[DD]>(sm);
    float* W1c        = sm + 2048;
    float (*W2c)[DD]  = reinterpret_cast<float (*)[DD]>(sm + 34816);
    float (*Us)[DD]   = reinterpret_cast<float (*)[DD]>(sm + 51200);   // Usp0
    float (*Usp1)[DD] = reinterpret_cast<float (*)[DD]>(sm + 53248);
    float (*lnS)[16]  = reinterpret_cast<float (*)[16]>(sm + 55296);
    float (*lnQ)[16]  = reinterpret_cast<float (*)[16]>(sm + 55328);

    const int tid = threadIdx.x;
    const int lane = tid & 31, wid = tid >> 5;
    const int kg = wid >> 2;            // warps 0-3 kg0, 4-7 kg1
    const int rg = (wid >> 1) & 1;
    const int cg = wid & 1;
    const int rg8 = rg * 8;
    const int c2 = cg * 64 + lane * 2;
    const int kb = kg * 64;             // k-offset within each 128 range
    const int row0 = blockIdx.x * 16;

    const uint32_t w1s = (uint32_t)__cvta_generic_to_shared(W1c);
    const uint32_t w2s = (uint32_t)__cvta_generic_to_shared(&W2c[0][0]);

    // chunk-0 weight loads (256 threads, 16 float4 each per buffer)
#pragma unroll
    for (int i = 0; i < 16; i++) {
        int t16 = tid + i * 256;
        int k = t16 >> 5, c4 = (t16 & 31) << 2;
        cp_async16(w1s + (uint32_t)(k * DD + c4) * 4, W1 + k * HH + c4);
    }
    cp_commit();
#pragma unroll
    for (int i = 0; i < 16; i++) {
        int t16 = tid + i * 256;
        int k = t16 >> 5, c4 = (t16 & 31) << 2;
        cp_async16(w2s + (uint32_t)(k * DD + c4) * 4, W2 + k * DD + c4);
    }
    cp_commit();

    // load h rows (doubles as residual): 2 float4 per thread
#pragma unroll
    for (int i = 0; i < 2; i++) {
        int idx4 = (tid + i * 256) * 4;
        *reinterpret_cast<float4*>(&hs[idx4 >> 7][idx4 & 127]) =
            *reinterpret_cast<const float4*>(&g_h[row0 * DD + idx4]);
    }

    float acc2[8][2];
#pragma unroll
    for (int r = 0; r < 8; r++) { acc2[r][0] = 0.f; acc2[r][1] = 0.f; }

    for (int ci = 0; ci < 4; ci++) {
        const int c0 = ci * 128;
        const float* W1b = W1c + (ci & 1) * 16384;

        cp_wait1();          // W1(ci) landed
        __syncthreads();     // + hs / Usp / buffer hazards

        // ---- ff1 partial: k in [kb, kb+64), thread = 8 rows x 2 cols ----
        float acc1[8][2];
#pragma unroll
        for (int r = 0; r < 8; r++) { acc1[r][0] = 0.f; acc1[r][1] = 0.f; }
#pragma unroll 2
        for (int k0 = kb; k0 < kb + 64; k0 += 4) {
            float a[8][4];
#pragma unroll
            for (int r = 0; r < 8; r++)
                *reinterpret_cast<float4*>(a[r]) =
                    *reinterpret_cast<const float4*>(&hs[rg8 + r][k0]);
#pragma unroll
            for (int kk = 0; kk < 4; kk++) {
                float2 w = *reinterpret_cast<const float2*>(&W1b[(k0 + kk) * DD + c2]);
#pragma unroll
                for (int r = 0; r < 8; r++) {
                    acc1[r][0] = fmaf(a[r][kk], w.x, acc1[r][0]);
                    acc1[r][1] = fmaf(a[r][kk], w.y, acc1[r][1]);
                }
            }
        }
        // publish raw partials
        {
            float (*Up)[DD] = kg ? Usp1 : Us;
#pragma unroll
            for (int r = 0; r < 8; r++) {
                float2 u;
                u.x = acc1[r][0];
                u.y = acc1[r][1];
                *reinterpret_cast<float2*>(&Up[rg8 + r][c2]) = u;
            }
        }
        __syncthreads();

        // ---- combine: Us = relu(Usp0 + Usp1 + b1), 2048 floats ----
#pragma unroll
        for (int i = 0; i < 2; i++) {
            int idx4 = (tid + i * 256) * 4;
            int r = idx4 >> 7, cc = idx4 & 127;
            float4 ua = *reinterpret_cast<const float4*>(&Us[r][cc]);
            float4 ub = *reinterpret_cast<const float4*>(&Usp1[r][cc]);
            float4 bb = *reinterpret_cast<const float4*>(&b1[c0 + cc]);
            float4 u;
            u.x = fmaxf(ua.x + ub.x + bb.x, 0.0f);
            u.y = fmaxf(ua.y + ub.y + bb.y, 0.0f);
            u.z = fmaxf(ua.z + ub.z + bb.z, 0.0f);
            u.w = fmaxf(ua.w + ub.w + bb.w, 0.0f);
            *reinterpret_cast<float4*>(&Us[r][cc]) = u;
        }

        // prefetch W1(ci+1) into the other buffer (overlaps ff2)
        if (ci < 3) {
            uint32_t dst = w1s + (uint32_t)(((ci + 1) & 1) * 16384) * 4;
            const float* src = W1 + c0 + 128;
#pragma unroll
            for (int i = 0; i < 16; i++) {
                int t16 = tid + i * 256;
                int k = t16 >> 5, c4 = (t16 & 31) << 2;
                cp_async16(dst + (uint32_t)(k * DD + c4) * 4, src + k * HH + c4);
            }
            cp_commit();
        }

        if (ci < 3) cp_wait1(); else cp_wait0();   // W2(ci) landed
        __syncthreads();                            // + Us final visible

        // ---- ff2 partial: acc2 += Us @ W2c over k in [kb, kb+64) ----
#pragma unroll 2
        for (int k0 = kb; k0 < kb + 64; k0 += 4) {
            float a[8][4];
#pragma unroll
            for (int r = 0; r < 8; r++)
                *reinterpret_cast<float4*>(a[r]) =
                    *reinterpret_cast<const float4*>(&Us[rg8 + r][k0]);
#pragma unroll
            for (int kk = 0; kk < 4; kk++) {
                float2 w = *reinterpret_cast<const float2*>(&W2c[k0 + kk][c2]);
#pragma unroll
                for (int r = 0; r < 8; r++) {
                    acc2[r][0] = fmaf(a[r][kk], w.x, acc2[r][0]);
                    acc2[r][1] = fmaf(a[r][kk], w.y, acc2[r][1]);
                }
            }
        }
        __syncthreads();    // W2c + Us fully consumed

        // prefetch W2(ci+1) (overlaps next ff1)
        if (ci < 3) {
            const float* src = W2 + (c0 + 128) * DD;
#pragma unroll
            for (int i = 0; i < 16; i++) {
                int t16 = tid + i * 256;
                int k = t16 >> 5, c4 = (t16 & 31) << 2;
                cp_async16(w2s + (uint32_t)(k * DD + c4) * 4, src + k * DD + c4);
            }
            cp_commit();
        }
    }

    // ---- epilogue: combine kg partials, +b2 +residual, LN (kg0 only) ----
    if (kg == 1) {
#pragma unroll
        for (int r = 0; r < 8; r++) {
            float2 u;
            u.x = acc2[r][0];
            u.y = acc2[r][1];
            *reinterpret_cast<float2*>(&Usp1[rg8 + r][c2]) = u;
        }
    }
    __syncthreads();

    if (kg == 0) {
        float v[8][2], s[8], q[8];
        float b20 = b2[c2], b21 = b2[c2 + 1];
#pragma unroll
        for (int r = 0; r < 8; r++) {
            v[r][0] = acc2[r][0] + Usp1[rg8 + r][c2] + b20 + hs[rg8 + r][c2];
            v[r][1] = acc2[r][1] + Usp1[rg8 + r][c2 + 1] + b21 + hs[rg8 + r][c2 + 1];
            s[r] = v[r][0] + v[r][1];
            q[r] = v[r][0] * v[r][0] + v[r][1] * v[r][1];
        }
#pragma unroll
        for (int o = 16; o > 0; o >>= 1)
#pragma unroll
            for (int r = 0; r < 8; r++) {
                s[r] += __shfl_xor_sync(0xffffffffu, s[r], o);
                q[r] += __shfl_xor_sync(0xffffffffu, q[r], o);
            }
        if (lane == 0)
#pragma unroll
            for (int r = 0; r < 8; r++) { lnS[cg][rg8 + r] = s[r]; lnQ[cg][rg8 + r] = q[r]; }
        bar_sync(1, 128);     // kg0's 4 warps
        float g0 = gf[c2], g1 = gf[c2 + 1], e0 = bgf[c2], e1 = bgf[c2 + 1];
#pragma unroll
        for (int r = 0; r < 8; r++) {
            float S = lnS[0][rg8 + r] + lnS[1][rg8 + r];
            float Q = lnQ[0][rg8 + r] + lnQ[1][rg8 + r];
            float mean = S * (1.0f / DD);
            float rstd = rsqrtf(Q * (1.0f / DD) - mean * mean + LN_EPS);
            float2 o;
            o.x = (v[r][0] - mean) * rstd * g0 + e0;
            o.y = (v[r][1] - mean) * rstd * g1 + e1;
            int row = row0 + rg8 + r;
            if (FINAL) *reinterpret_cast<float2*>(&out[row * DD + c2]) = o;
            else       *reinterpret_cast<float2*>(&g_h[row * DD + c2]) = o;
        }
    }
}

extern "C" void kernel_launch(void* const* d_in, const int* in_sizes, int n_in,
                              void* d_out, int out_size) {
    const float* x   = (const float*)d_in[0];   // (8,256,2)
    const float* We  = (const float*)d_in[1];   // (2,128)
    const float* be  = (const float*)d_in[2];
    const float* ge  = (const float*)d_in[3];
    const float* bge = (const float*)d_in[4];
    const float* Wp  = (const float*)d_in[5];   // (2,256,128)
    const float* bp  = (const float*)d_in[6];
    const float* gp  = (const float*)d_in[7];
    const float* bgp = (const float*)d_in[8];
    const float* W1  = (const float*)d_in[9];   // (2,128,512)
    const float* b1  = (const float*)d_in[10];
    const float* W2  = (const float*)d_in[11];  // (2,512,128)
    const float* b2  = (const float*)d_in[12];
    const float* gf  = (const float*)d_in[13];
    const float* bgf = (const float*)d_in[14];
    float* out = (float*)d_out;                 // (8,256,128) fp32

    cudaFuncSetAttribute(pool_kernel,
                         cudaFuncAttributeMaxDynamicSharedMemorySize, POOL_SMEM);
    cudaFuncSetAttribute(ff_fused_kernel<false>,
                         cudaFuncAttributeMaxDynamicSharedMemorySize, FF_SMEM);
    cudaFuncSetAttribute(ff_fused_kernel<true>,
                         cudaFuncAttributeMaxDynamicSharedMemorySize, FF_SMEM);

    embed_ln_kernel<<<T_TOK, 128>>>(x, We, be, ge, bge);

    for (int i = 0; i < 2; i++) {
        stats_kernel<<<NB, dim3(128, 4)>>>();

        pool_kernel<<<T_TOK / 16, 512, POOL_SMEM>>>(
            Wp + i * 2 * DD * DD, bp + i * DD, gp + i * DD, bgp + i * DD);

        if (i == 1)
            ff_fused_kernel<true><<<T_TOK / 16, 256, FF_SMEM>>>(
                W1 + i * DD * HH, b1 + i * HH, W2 + i * HH * DD, b2 + i * DD,
                gf + i * DD, bgf + i * DD, out);
        else
            ff_fused_kernel<false><<<T_TOK / 16, 256, FF_SMEM>>>(
                W1 + i * DD * HH, b1 + i * HH, W2 + i * HH * DD, b2 + i * DD,
                gf + i * DD, bgf + i * DD, nullptr);
    }
}